// round 1
// baseline (speedup 1.0000x reference)
#include <cuda_runtime.h>
#include <cuda_bf16.h>
#include <cstdint>

// ============================================================================
// SpatialGAT on GB300 — baseline round 1
//
// Stage 1: h = x @ W                        (fp32 tiled GEMM -> g_h [N][256])
// Stage 2: src/dst logit dots + exp tables  (g_src, g_P=exp(src), g_P2=exp(.2src),
//                                            g_dst, g_Q=exp(dst), g_Q2=exp(.2dst))
// Stage 3: fused masked-softmax aggregation (no MUFU, no alpha materialization)
//          out[i,f] = (sum_j w_ij * h[j,f]) / (sum_j w_ij) + bias[f]
//          w_ij = adj_ij * ( s>0 ? P_i*Q_j : P2_i*Q2_j ),  s = src_i + dst_j
// ============================================================================

#define N_NODES 8192
#define F_OUT   256     // HEADS*HEAD_DIM
#define F_IN    256
#define NEG_SLOPE 0.2f

// scratch (device globals: allocation-free rule)
__device__ float g_h[N_NODES * F_OUT];     // 8 MB
__device__ float g_src[N_NODES * 4];
__device__ float g_dst[N_NODES * 4];
__device__ float g_P [N_NODES * 4];
__device__ float g_P2[N_NODES * 4];
__device__ float g_Q [N_NODES * 4];
__device__ float g_Q2[N_NODES * 4];

// ---------------------------------------------------------------------------
// packed fp32x2 helpers (sm_103a FFMA2 — only reachable via PTX fma.rn.f32x2)
// ---------------------------------------------------------------------------
__device__ __forceinline__ unsigned long long pack_f32x2(float lo, float hi) {
    unsigned long long r;
    asm("mov.b64 %0, {%1, %2};" : "=l"(r) : "f"(lo), "f"(hi));
    return r;
}
__device__ __forceinline__ unsigned long long ffma2(unsigned long long a,
                                                    unsigned long long b,
                                                    unsigned long long c) {
    unsigned long long d;
    asm("fma.rn.f32x2 %0, %1, %2, %3;" : "=l"(d) : "l"(a), "l"(b), "l"(c));
    return d;
}
__device__ __forceinline__ void unpack_f32x2(unsigned long long v, float& lo, float& hi) {
    asm("mov.b64 {%0, %1}, %2;" : "=f"(lo), "=f"(hi) : "l"(v));
}

// ---------------------------------------------------------------------------
// Stage 1: h[n][f] = sum_k x[n][k] * W[k][f]   (W is [256][4*64] row-major)
// 64x64 block tile, 256 threads, 4x4 per-thread microtile, K-chunks of 16.
// ---------------------------------------------------------------------------
__global__ void __launch_bounds__(256) transform_kernel(const float* __restrict__ x,
                                                        const float* __restrict__ W) {
    __shared__ float xs[64][16];
    __shared__ float ws[16][64];

    const int tid = threadIdx.x;
    const int i0 = blockIdx.x * 64;
    const int j0 = blockIdx.y * 64;
    const int tx = tid & 15;     // 0..15 -> 4 cols each
    const int ty = tid >> 4;     // 0..15 -> 4 rows each

    float acc[4][4];
#pragma unroll
    for (int r = 0; r < 4; r++)
#pragma unroll
        for (int c = 0; c < 4; c++) acc[r][c] = 0.f;

    for (int k0 = 0; k0 < F_IN; k0 += 16) {
        {
            int r = tid >> 2, c = (tid & 3) << 2;
            float4 v = *(const float4*)&x[(size_t)(i0 + r) * F_IN + k0 + c];
            *(float4*)&xs[r][c] = v;
        }
        {
            int l = tid << 2;
            int c = l >> 6, j = l & 63;
            float4 v = *(const float4*)&W[(size_t)(k0 + c) * F_OUT + j0 + j];
            *(float4*)&ws[c][j] = v;
        }
        __syncthreads();
#pragma unroll
        for (int kk = 0; kk < 16; kk++) {
            float a[4];
#pragma unroll
            for (int r = 0; r < 4; r++) a[r] = xs[ty * 4 + r][kk];
            float4 bv = *(const float4*)&ws[kk][tx * 4];
#pragma unroll
            for (int r = 0; r < 4; r++) {
                acc[r][0] = fmaf(a[r], bv.x, acc[r][0]);
                acc[r][1] = fmaf(a[r], bv.y, acc[r][1]);
                acc[r][2] = fmaf(a[r], bv.z, acc[r][2]);
                acc[r][3] = fmaf(a[r], bv.w, acc[r][3]);
            }
        }
        __syncthreads();
    }
#pragma unroll
    for (int r = 0; r < 4; r++) {
        float4 v = make_float4(acc[r][0], acc[r][1], acc[r][2], acc[r][3]);
        *(float4*)&g_h[(size_t)(i0 + ty * 4 + r) * F_OUT + j0 + tx * 4] = v;
    }
}

// ---------------------------------------------------------------------------
// Stage 2: per (node, head) logit dots + exp tables
// ---------------------------------------------------------------------------
__global__ void __launch_bounds__(256) attn_vec_kernel(const float* __restrict__ a_src,
                                                       const float* __restrict__ a_dst) {
    int idx = blockIdx.x * blockDim.x + threadIdx.x;   // (n*4 + h), 32768 total
    if (idx >= N_NODES * 4) return;
    int n = idx >> 2, h = idx & 3;
    const float* hp = &g_h[(size_t)n * F_OUT + h * 64];
    const float* as = &a_src[h * 64];
    const float* ad = &a_dst[h * 64];
    float s = 0.f, d = 0.f;
#pragma unroll 8
    for (int k = 0; k < 64; k++) {
        float v = hp[k];
        s = fmaf(v, as[k], s);
        d = fmaf(v, ad[k], d);
    }
    g_src[idx] = s;
    g_dst[idx] = d;
    g_P [idx] = expf(s);
    g_P2[idx] = expf(NEG_SLOPE * s);
    g_Q [idx] = expf(d);
    g_Q2[idx] = expf(NEG_SLOPE * d);
}

// ---------------------------------------------------------------------------
// Stage 3: fused aggregation.
// Block = 256 threads = 32 target rows (iy) x 8 dim-groups (g).
// Thread owns 32 consecutive output dims of one row (single head => one w/jj).
// j processed in tiles of BJ=32 staged in SMEM.
// ---------------------------------------------------------------------------
#define BI 32
#define BJ 32

__global__ void __launch_bounds__(256) aggregate_kernel(const int* __restrict__ adj,
                                                        const float* __restrict__ bias,
                                                        float* __restrict__ out) {
    __shared__ float h_sh[BJ * F_OUT];      // 32 KB
    __shared__ float dst_sh[BJ * 4];
    __shared__ float q_sh [BJ * 4];
    __shared__ float q2_sh[BJ * 4];
    __shared__ int   adj_sh[BI * BJ];       // 4 KB

    const int tid  = threadIdx.x;
    const int iy   = tid >> 3;          // local row 0..31
    const int g    = tid & 7;           // dim group: dims [g*32, g*32+32)
    const int head = g >> 1;
    const int i    = blockIdx.x * BI + iy;
    const long irow = (long)i * N_NODES;

    const float src_i = g_src[i * 4 + head];
    const float Pi    = g_P [i * 4 + head];
    const float Pi2   = g_P2[i * 4 + head];

    unsigned long long acc[16];
#pragma unroll
    for (int k = 0; k < 16; k++) acc[k] = 0ull;   // +0.0f,+0.0f
    float Z = 0.f;

    for (int j0 = 0; j0 < N_NODES; j0 += BJ) {
        // --- stage tile ---
        {
            // h tile: BJ*256 floats contiguous
            const float4* src4 = (const float4*)&g_h[(size_t)j0 * F_OUT];
            float4* dst4 = (float4*)h_sh;
#pragma unroll
            for (int t = 0; t < (BJ * F_OUT) / (256 * 4); t++)
                dst4[tid + t * 256] = src4[tid + t * 256];
            if (tid < BJ * 4) {
                dst_sh[tid] = g_dst[j0 * 4 + tid];
                q_sh [tid]  = g_Q [j0 * 4 + tid];
                q2_sh[tid]  = g_Q2[j0 * 4 + tid];
            }
            // adj tile: BI x BJ ints, int4 loads
            int r = tid >> 3, c = (tid & 7) << 2;
            *(int4*)&adj_sh[r * BJ + c] =
                *(const int4*)&adj[(long)(blockIdx.x * BI + r) * N_NODES + j0 + c];
        }
        __syncthreads();

#pragma unroll 4
        for (int jj = 0; jj < BJ; jj++) {
            float s = src_i + dst_sh[jj * 4 + head];
            float w = (s > 0.f) ? (Pi * q_sh[jj * 4 + head])
                                : (Pi2 * q2_sh[jj * 4 + head]);
            w *= (float)adj_sh[iy * BJ + jj];
            Z += w;
            unsigned long long w2 = pack_f32x2(w, w);
            const double* hp = (const double*)&h_sh[jj * F_OUT + (g << 5)];
#pragma unroll
            for (int k = 0; k < 16; k++) {
                acc[k] = ffma2(w2, __double_as_longlong(hp[k]), acc[k]);
            }
        }
        __syncthreads();
    }

    const float invZ = 1.f / Z;
    const int f0 = g << 5;
#pragma unroll
    for (int k4 = 0; k4 < 8; k4++) {
        float a0, a1, a2, a3;
        unpack_f32x2(acc[k4 * 2 + 0], a0, a1);
        unpack_f32x2(acc[k4 * 2 + 1], a2, a3);
        float4 b = *(const float4*)&bias[f0 + k4 * 4];
        float4 o;
        o.x = a0 * invZ + b.x;
        o.y = a1 * invZ + b.y;
        o.z = a2 * invZ + b.z;
        o.w = a3 * invZ + b.w;
        *(float4*)&out[(size_t)i * F_OUT + f0 + k4 * 4] = o;
    }
}

// ---------------------------------------------------------------------------
extern "C" void kernel_launch(void* const* d_in, const int* in_sizes, int n_in,
                              void* d_out, int out_size) {
    const float* x     = (const float*)d_in[0];
    const int*   adj   = (const int*)  d_in[1];
    const float* W     = (const float*)d_in[2];
    const float* a_src = (const float*)d_in[3];
    const float* a_dst = (const float*)d_in[4];
    const float* bias  = (const float*)d_in[5];
    float* out = (float*)d_out;

    transform_kernel<<<dim3(N_NODES / 64, F_OUT / 64), 256>>>(x, W);
    attn_vec_kernel<<<(N_NODES * 4) / 256, 256>>>(a_src, a_dst);
    aggregate_kernel<<<N_NODES / BI, 256>>>(adj, bias, out);
}

// round 2
// speedup vs baseline: 15.7086x; 15.7086x over previous
#include <cuda_runtime.h>
#include <cuda_bf16.h>
#include <cstdint>

// ============================================================================
// SpatialGAT on GB300 — round 2: GEMM-structured fused aggregation
//
// Stage 1: h = x @ W                         (fp32 tiled GEMM -> g_h [N][256])
// Stage 2: logit dots + exp tables, HEAD-MAJOR layout [4][N]
// Stage 3: per (i-tile=128, head): w tile [32 j][128 i] built in smem once,
//          then register-blocked FFMA2 GEMM  out += w^T @ h_head
//          w_ij = adj_ij ? ( s>0 ? P_i*Q_j : P2_i*Q2_j ) : 0,  s = src_i+dst_j
// ============================================================================

#define N_NODES 8192
#define F_OUT   256
#define F_IN    256
#define NEG_SLOPE 0.2f
#define BI 128
#define BJ 32

// scratch (device globals: allocation-free rule)
__device__ float g_h[N_NODES * F_OUT];        // 8 MB
__device__ float g_sT [4 * N_NODES];          // head-major tables
__device__ float g_PT [4 * N_NODES];
__device__ float g_P2T[4 * N_NODES];
__device__ float g_dT [4 * N_NODES];
__device__ float g_QT [4 * N_NODES];
__device__ float g_Q2T[4 * N_NODES];

// ---------------------------------------------------------------------------
// packed fp32x2 helpers
// ---------------------------------------------------------------------------
__device__ __forceinline__ unsigned long long pack_f32x2(float lo, float hi) {
    unsigned long long r;
    asm("mov.b64 %0, {%1, %2};" : "=l"(r) : "f"(lo), "f"(hi));
    return r;
}
__device__ __forceinline__ unsigned long long ffma2(unsigned long long a,
                                                    unsigned long long b,
                                                    unsigned long long c) {
    unsigned long long d;
    asm("fma.rn.f32x2 %0, %1, %2, %3;" : "=l"(d) : "l"(a), "l"(b), "l"(c));
    return d;
}
__device__ __forceinline__ void unpack_f32x2(unsigned long long v, float& lo, float& hi) {
    asm("mov.b64 {%0, %1}, %2;" : "=f"(lo), "=f"(hi) : "l"(v));
}

// ---------------------------------------------------------------------------
// Stage 1: h[n][f] = sum_k x[n][k] * W[k][f]
// ---------------------------------------------------------------------------
__global__ void __launch_bounds__(256) transform_kernel(const float* __restrict__ x,
                                                        const float* __restrict__ W) {
    __shared__ float xs[64][16];
    __shared__ float ws[16][64];

    const int tid = threadIdx.x;
    const int i0 = blockIdx.x * 64;
    const int j0 = blockIdx.y * 64;
    const int tx = tid & 15;
    const int ty = tid >> 4;

    float acc[4][4];
#pragma unroll
    for (int r = 0; r < 4; r++)
#pragma unroll
        for (int c = 0; c < 4; c++) acc[r][c] = 0.f;

    for (int k0 = 0; k0 < F_IN; k0 += 16) {
        {
            int r = tid >> 2, c = (tid & 3) << 2;
            float4 v = *(const float4*)&x[(size_t)(i0 + r) * F_IN + k0 + c];
            *(float4*)&xs[r][c] = v;
        }
        {
            int l = tid << 2;
            int c = l >> 6, j = l & 63;
            float4 v = *(const float4*)&W[(size_t)(k0 + c) * F_OUT + j0 + j];
            *(float4*)&ws[c][j] = v;
        }
        __syncthreads();
#pragma unroll
        for (int kk = 0; kk < 16; kk++) {
            float a[4];
#pragma unroll
            for (int r = 0; r < 4; r++) a[r] = xs[ty * 4 + r][kk];
            float4 bv = *(const float4*)&ws[kk][tx * 4];
#pragma unroll
            for (int r = 0; r < 4; r++) {
                acc[r][0] = fmaf(a[r], bv.x, acc[r][0]);
                acc[r][1] = fmaf(a[r], bv.y, acc[r][1]);
                acc[r][2] = fmaf(a[r], bv.z, acc[r][2]);
                acc[r][3] = fmaf(a[r], bv.w, acc[r][3]);
            }
        }
        __syncthreads();
    }
#pragma unroll
    for (int r = 0; r < 4; r++) {
        float4 v = make_float4(acc[r][0], acc[r][1], acc[r][2], acc[r][3]);
        *(float4*)&g_h[(size_t)(i0 + ty * 4 + r) * F_OUT + j0 + tx * 4] = v;
    }
}

// ---------------------------------------------------------------------------
// Stage 2: logit dots + exp tables, written HEAD-MAJOR
// ---------------------------------------------------------------------------
__global__ void __launch_bounds__(256) attn_vec_kernel(const float* __restrict__ a_src,
                                                       const float* __restrict__ a_dst) {
    int idx = blockIdx.x * blockDim.x + threadIdx.x;   // (n*4 + h)
    if (idx >= N_NODES * 4) return;
    int n = idx >> 2, h = idx & 3;
    const float* hp = &g_h[(size_t)n * F_OUT + h * 64];
    const float* as = &a_src[h * 64];
    const float* ad = &a_dst[h * 64];
    float s = 0.f, d = 0.f;
#pragma unroll 8
    for (int k = 0; k < 64; k++) {
        float v = hp[k];
        s = fmaf(v, as[k], s);
        d = fmaf(v, ad[k], d);
    }
    int o = h * N_NODES + n;
    g_sT [o] = s;
    g_dT [o] = d;
    g_PT [o] = expf(s);
    g_P2T[o] = expf(NEG_SLOPE * s);
    g_QT [o] = expf(d);
    g_Q2T[o] = expf(NEG_SLOPE * d);
}

// ---------------------------------------------------------------------------
// Stage 3: block = (i-tile of 128 rows) x (one head, 64 dims), 256 threads.
// microtile: 8 rows x 4 cols per thread (rows paired for FFMA2).
// ---------------------------------------------------------------------------
__global__ void __launch_bounds__(256, 2)
aggregate_kernel(const int* __restrict__ adj,
                 const float* __restrict__ bias,
                 float* __restrict__ out) {
    __shared__ float  w_sh[BJ][132];     // [jj][i], padded (16.9 KB)
    __shared__ float2 hd_sh[BJ][66];     // [jj][c] value duplicated (16.9 KB)
    __shared__ float  z_sh[BI];

    const int tid  = threadIdx.x;
    const int head = blockIdx.y;
    const int i0   = blockIdx.x * BI;

    // staging roles
    const int c4 = tid & 7;       // adj col group (4 cols) / h col group (8 cols)
    const int rr = tid >> 3;      // 0..31 ; adj rows rr+32p / h row

    // compute roles
    const int ty = tid >> 4;      // rows ty*8..+7
    const int tx = tid & 15;      // cols tx*4..+3

    if (tid < BI) z_sh[tid] = 0.f;

    // per-row src-side constants (this thread's w rows: rr+32p)
    float si[4], Pi[4], Pi2[4];
#pragma unroll
    for (int p = 0; p < 4; p++) {
        int row = head * N_NODES + i0 + rr + 32 * p;
        si[p]  = g_sT [row];
        Pi[p]  = g_PT [row];
        Pi2[p] = g_P2T[row];
    }

    unsigned long long acc[16];
#pragma unroll
    for (int k = 0; k < 16; k++) acc[k] = 0ull;
    float zpart[4] = {0.f, 0.f, 0.f, 0.f};

    int4 a_pf[4];
    float4 h_pf0, h_pf1;

#define LOAD_TILE(J0)                                                               \
    do {                                                                            \
        _Pragma("unroll")                                                           \
        for (int p = 0; p < 4; p++)                                                 \
            a_pf[p] = *(const int4*)&adj[(size_t)(i0 + rr + 32 * p) * N_NODES +     \
                                          (J0) + c4 * 4];                           \
        const float* hb = &g_h[(size_t)((J0) + rr) * F_OUT + head * 64 + c4 * 8];   \
        h_pf0 = *(const float4*)hb;                                                 \
        h_pf1 = *(const float4*)(hb + 4);                                           \
    } while (0)

    LOAD_TILE(0);

    for (int t = 0; t < N_NODES / BJ; t++) {
        const int j0 = t * BJ;
        // dst-side tables for this tile's 4 cols (L1-hot, head-major => vectorized)
        const int jb = head * N_NODES + j0 + c4 * 4;
        float4 dj  = *(const float4*)&g_dT [jb];
        float4 Qj  = *(const float4*)&g_QT [jb];
        float4 Q2j = *(const float4*)&g_Q2T[jb];

        __syncthreads();   // previous inner loop done reading smem

        // ---- build w tile (transposed) + Z partials ----
#pragma unroll
        for (int p = 0; p < 4; p++) {
            const int row = rr + 32 * p;
            const int4 a = a_pf[p];
            float s, w;
            s = si[p] + dj.x;
            w = (a.x != 0) ? ((s > 0.f) ? Pi[p] * Qj.x : Pi2[p] * Q2j.x) : 0.f;
            zpart[p] += w; w_sh[c4 * 4 + 0][row] = w;
            s = si[p] + dj.y;
            w = (a.y != 0) ? ((s > 0.f) ? Pi[p] * Qj.y : Pi2[p] * Q2j.y) : 0.f;
            zpart[p] += w; w_sh[c4 * 4 + 1][row] = w;
            s = si[p] + dj.z;
            w = (a.z != 0) ? ((s > 0.f) ? Pi[p] * Qj.z : Pi2[p] * Q2j.z) : 0.f;
            zpart[p] += w; w_sh[c4 * 4 + 2][row] = w;
            s = si[p] + dj.w;
            w = (a.w != 0) ? ((s > 0.f) ? Pi[p] * Qj.w : Pi2[p] * Q2j.w) : 0.f;
            zpart[p] += w; w_sh[c4 * 4 + 3][row] = w;
        }
        // ---- stage h tile, value-duplicated for splat-free FFMA2 ----
        hd_sh[rr][c4 * 8 + 0] = make_float2(h_pf0.x, h_pf0.x);
        hd_sh[rr][c4 * 8 + 1] = make_float2(h_pf0.y, h_pf0.y);
        hd_sh[rr][c4 * 8 + 2] = make_float2(h_pf0.z, h_pf0.z);
        hd_sh[rr][c4 * 8 + 3] = make_float2(h_pf0.w, h_pf0.w);
        hd_sh[rr][c4 * 8 + 4] = make_float2(h_pf1.x, h_pf1.x);
        hd_sh[rr][c4 * 8 + 5] = make_float2(h_pf1.y, h_pf1.y);
        hd_sh[rr][c4 * 8 + 6] = make_float2(h_pf1.z, h_pf1.z);
        hd_sh[rr][c4 * 8 + 7] = make_float2(h_pf1.w, h_pf1.w);

        __syncthreads();

        if (t + 1 < N_NODES / BJ) LOAD_TILE(j0 + BJ);   // overlap with inner loop

        // ---- inner GEMM: 32 jj x (8 rows x 4 cols) ----
#pragma unroll 8
        for (int jj = 0; jj < BJ; jj++) {
            const float* wrow = &w_sh[jj][ty * 8];
            float4 w0 = *(const float4*)wrow;
            float4 w1 = *(const float4*)(wrow + 4);
            float4 u0 = *(const float4*)&hd_sh[jj][tx * 4];       // (h0,h0,h1,h1)
            float4 u1 = *(const float4*)&hd_sh[jj][tx * 4 + 2];   // (h2,h2,h3,h3)

            unsigned long long w2[4], h2[4];
            w2[0] = pack_f32x2(w0.x, w0.y);
            w2[1] = pack_f32x2(w0.z, w0.w);
            w2[2] = pack_f32x2(w1.x, w1.y);
            w2[3] = pack_f32x2(w1.z, w1.w);
            h2[0] = pack_f32x2(u0.x, u0.y);
            h2[1] = pack_f32x2(u0.z, u0.w);
            h2[2] = pack_f32x2(u1.x, u1.y);
            h2[3] = pack_f32x2(u1.z, u1.w);
#pragma unroll
            for (int rp = 0; rp < 4; rp++)
#pragma unroll
                for (int c = 0; c < 4; c++)
                    acc[rp * 4 + c] = ffma2(w2[rp], h2[c], acc[rp * 4 + c]);
        }
    }

    // ---- Z reduction ----
#pragma unroll
    for (int p = 0; p < 4; p++) atomicAdd(&z_sh[rr + 32 * p], zpart[p]);
    __syncthreads();

    // ---- normalize + bias + store ----
    const float4 bv = *(const float4*)&bias[head * 64 + tx * 4];
#pragma unroll
    for (int r = 0; r < 8; r++) {
        const int row = ty * 8 + r;
        const float invZ = __frcp_rn(z_sh[row]);
        const int rp = r >> 1;
        float lo, hi, v0, v1, v2, v3;
        unpack_f32x2(acc[rp * 4 + 0], lo, hi); v0 = (r & 1) ? hi : lo;
        unpack_f32x2(acc[rp * 4 + 1], lo, hi); v1 = (r & 1) ? hi : lo;
        unpack_f32x2(acc[rp * 4 + 2], lo, hi); v2 = (r & 1) ? hi : lo;
        unpack_f32x2(acc[rp * 4 + 3], lo, hi); v3 = (r & 1) ? hi : lo;
        float4 o;
        o.x = fmaf(v0, invZ, bv.x);
        o.y = fmaf(v1, invZ, bv.y);
        o.z = fmaf(v2, invZ, bv.z);
        o.w = fmaf(v3, invZ, bv.w);
        *(float4*)&out[(size_t)(i0 + row) * F_OUT + head * 64 + tx * 4] = o;
    }
#undef LOAD_TILE
}

// ---------------------------------------------------------------------------
extern "C" void kernel_launch(void* const* d_in, const int* in_sizes, int n_in,
                              void* d_out, int out_size) {
    const float* x     = (const float*)d_in[0];
    const int*   adj   = (const int*)  d_in[1];
    const float* W     = (const float*)d_in[2];
    const float* a_src = (const float*)d_in[3];
    const float* a_dst = (const float*)d_in[4];
    const float* bias  = (const float*)d_in[5];
    float* out = (float*)d_out;

    transform_kernel<<<dim3(N_NODES / 64, F_OUT / 64), 256>>>(x, W);
    attn_vec_kernel<<<(N_NODES * 4) / 256, 256>>>(a_src, a_dst);
    aggregate_kernel<<<dim3(N_NODES / BI, 4), 256>>>(adj, bias, out);
}

// round 6
// speedup vs baseline: 87.1464x; 5.5477x over previous
#include <cuda_runtime.h>
#include <cuda_fp16.h>
#include <cstdint>

// ============================================================================
// SpatialGAT on GB300 — round 4: HMMA (mma.sync f16) aggregation
//   (tcgen05 is sm_103a-feature-gated; harness compiles via compute_103 → use
//    base-ISA mma.sync.m16n8k16 which still runs on the tensor pipe)
//
// Stage 1: h = x @ W (fp32) -> g_h fp32 + g_hf f16 copy
// Stage 2: P=exp(src),P2=exp(.2s),Q=exp(dst),Q2=exp(.2d)  f16 head-major
// Stage 3: pack adj -> bitmask g_adjb [N][N/32]
// Stage 4: per (i-tile 128, head): w_ij = bit * max(Pi*Qj, P2i*Q2j)  (f16)
//          out[128x64] = w[128x8192] @ hf[8192x64] via mma.sync, Z from build,
//          epilogue out = acc/Z + bias.
// ============================================================================

#define NN      8192
#define FOUT    256
#define FIN     256
#define HEADS   4
#define NEG_SLOPE 0.2f
#define BI      128
#define BJ      64
#define NCHUNK  (NN / BJ)

__device__ float    g_h [NN * FOUT];            // 8 MB fp32
__device__ __half   g_hf[NN * FOUT];            // 4 MB f16
__device__ __half   g_PT [HEADS * NN];
__device__ __half   g_P2T[HEADS * NN];
__device__ __half   g_QT [HEADS * NN];
__device__ __half   g_Q2T[HEADS * NN];
__device__ unsigned g_adjb[NN * (NN / 32)];     // 8 MB bitmask

// ---------------------------------------------------------------------------
// helpers
// ---------------------------------------------------------------------------
__device__ __forceinline__ uint32_t smem_u32(const void* p) {
    uint32_t a;
    asm("{ .reg .u64 t; cvta.to.shared.u64 t, %1; cvt.u32.u64 %0, t; }"
        : "=r"(a) : "l"(p));
    return a;
}
__device__ __forceinline__ uint32_t hmul2_(uint32_t a, uint32_t b) {
    uint32_t d; asm("mul.f16x2 %0, %1, %2;" : "=r"(d) : "r"(a), "r"(b)); return d;
}
__device__ __forceinline__ uint32_t hmax2_(uint32_t a, uint32_t b) {
    uint32_t d; asm("max.f16x2 %0, %1, %2;" : "=r"(d) : "r"(a), "r"(b)); return d;
}
__device__ __forceinline__ uint32_t hadd2_(uint32_t a, uint32_t b) {
    uint32_t d; asm("add.f16x2 %0, %1, %2;" : "=r"(d) : "r"(a), "r"(b)); return d;
}
__device__ __forceinline__ uint32_t splat16(unsigned short h) {
    uint32_t r; asm("mov.b32 %0, {%1, %1};" : "=r"(r) : "h"(h)); return r;
}
__device__ __forceinline__ void ldsm_x4(uint32_t& r0, uint32_t& r1, uint32_t& r2,
                                        uint32_t& r3, uint32_t addr) {
    asm volatile("ldmatrix.sync.aligned.m8n8.x4.shared.b16 {%0,%1,%2,%3}, [%4];"
                 : "=r"(r0), "=r"(r1), "=r"(r2), "=r"(r3) : "r"(addr));
}
__device__ __forceinline__ void ldsm_x4_t(uint32_t& r0, uint32_t& r1, uint32_t& r2,
                                          uint32_t& r3, uint32_t addr) {
    asm volatile("ldmatrix.sync.aligned.m8n8.x4.trans.shared.b16 {%0,%1,%2,%3}, [%4];"
                 : "=r"(r0), "=r"(r1), "=r"(r2), "=r"(r3) : "r"(addr));
}
__device__ __forceinline__ void mma16816(float* c, uint32_t a0, uint32_t a1,
                                         uint32_t a2, uint32_t a3,
                                         uint32_t b0, uint32_t b1) {
    asm volatile(
        "mma.sync.aligned.m16n8k16.row.col.f32.f16.f16.f32 "
        "{%0,%1,%2,%3}, {%4,%5,%6,%7}, {%8,%9}, {%0,%1,%2,%3};"
        : "+f"(c[0]), "+f"(c[1]), "+f"(c[2]), "+f"(c[3])
        : "r"(a0), "r"(a1), "r"(a2), "r"(a3), "r"(b0), "r"(b1));
}
#define SWZ(off) ((off) ^ (((off) >> 3) & 0x70))

// ---------------------------------------------------------------------------
// Stage 1: h = x @ W (fp32 + f16 copy)
// ---------------------------------------------------------------------------
__global__ void __launch_bounds__(256) transform_kernel(const float* __restrict__ x,
                                                        const float* __restrict__ W) {
    __shared__ float xs[64][16];
    __shared__ float ws[16][64];
    const int tid = threadIdx.x;
    const int i0 = blockIdx.x * 64, j0 = blockIdx.y * 64;
    const int tx = tid & 15, ty = tid >> 4;

    float acc[4][4];
#pragma unroll
    for (int r = 0; r < 4; r++)
#pragma unroll
        for (int c = 0; c < 4; c++) acc[r][c] = 0.f;

    for (int k0 = 0; k0 < FIN; k0 += 16) {
        {
            int r = tid >> 2, c = (tid & 3) << 2;
            *(float4*)&xs[r][c] = *(const float4*)&x[(size_t)(i0 + r) * FIN + k0 + c];
        }
        {
            int l = tid << 2, c = l >> 6, j = l & 63;
            *(float4*)&ws[c][j] = *(const float4*)&W[(size_t)(k0 + c) * FOUT + j0 + j];
        }
        __syncthreads();
#pragma unroll
        for (int kk = 0; kk < 16; kk++) {
            float a[4];
#pragma unroll
            for (int r = 0; r < 4; r++) a[r] = xs[ty * 4 + r][kk];
            float4 bv = *(const float4*)&ws[kk][tx * 4];
#pragma unroll
            for (int r = 0; r < 4; r++) {
                acc[r][0] = fmaf(a[r], bv.x, acc[r][0]);
                acc[r][1] = fmaf(a[r], bv.y, acc[r][1]);
                acc[r][2] = fmaf(a[r], bv.z, acc[r][2]);
                acc[r][3] = fmaf(a[r], bv.w, acc[r][3]);
            }
        }
        __syncthreads();
    }
#pragma unroll
    for (int r = 0; r < 4; r++) {
        size_t o = (size_t)(i0 + ty * 4 + r) * FOUT + j0 + tx * 4;
        *(float4*)&g_h[o] = make_float4(acc[r][0], acc[r][1], acc[r][2], acc[r][3]);
        __half2 h01 = __floats2half2_rn(acc[r][0], acc[r][1]);
        __half2 h23 = __floats2half2_rn(acc[r][2], acc[r][3]);
        uint2 hv;
        hv.x = *(uint32_t*)&h01;
        hv.y = *(uint32_t*)&h23;
        *(uint2*)&g_hf[o] = hv;
    }
}

// ---------------------------------------------------------------------------
// Stage 2: exp tables (f16, head-major)
// ---------------------------------------------------------------------------
__global__ void __launch_bounds__(256) attn_vec_kernel(const float* __restrict__ a_src,
                                                       const float* __restrict__ a_dst) {
    int idx = blockIdx.x * blockDim.x + threadIdx.x;
    if (idx >= NN * HEADS) return;
    int n = idx >> 2, h = idx & 3;
    const float* hp = &g_h[(size_t)n * FOUT + h * 64];
    const float* as = &a_src[h * 64];
    const float* ad = &a_dst[h * 64];
    float s = 0.f, d = 0.f;
#pragma unroll 8
    for (int k = 0; k < 64; k++) {
        float v = hp[k];
        s = fmaf(v, as[k], s);
        d = fmaf(v, ad[k], d);
    }
    int o = h * NN + n;
    g_PT [o] = __float2half_rn(expf(s));
    g_P2T[o] = __float2half_rn(expf(NEG_SLOPE * s));
    g_QT [o] = __float2half_rn(expf(d));
    g_Q2T[o] = __float2half_rn(expf(NEG_SLOPE * d));
}

// ---------------------------------------------------------------------------
// Stage 3: pack adj -> bitmask
// ---------------------------------------------------------------------------
__global__ void __launch_bounds__(256) pack_kernel(const int* __restrict__ adj) {
    int word = blockIdx.x * 256 + threadIdx.x;
    const int4* p = (const int4*)&adj[(size_t)word * 32];
    unsigned m = 0;
#pragma unroll
    for (int k = 0; k < 8; k++) {
        int4 v = p[k];
        m |= (unsigned)(v.x != 0) << (4 * k + 0);
        m |= (unsigned)(v.y != 0) << (4 * k + 1);
        m |= (unsigned)(v.z != 0) << (4 * k + 2);
        m |= (unsigned)(v.w != 0) << (4 * k + 3);
    }
    g_adjb[word] = m;
}

// ---------------------------------------------------------------------------
// Stage 4: HMMA aggregation.
// dyn smem: W0/W1 16KB each, B0/B1 8KB each, Z 1KB, LUT 128B
// ---------------------------------------------------------------------------
#define SM_W0   0
#define SM_W1   16384
#define SM_B0   32768
#define SM_B1   40960
#define SM_Z    49152
#define SM_LUT  50176
#define SM_TOTAL 50304

extern __shared__ unsigned char dsm[];

__global__ void __launch_bounds__(256, 2)
aggregate_kernel(const float* __restrict__ bias, float* __restrict__ out) {
    const int tid  = threadIdx.x;
    const int lane = tid & 31;
    const int wid  = tid >> 5;
    const int head = blockIdx.y;
    const int i0   = blockIdx.x * BI;
    const uint32_t sb = smem_u32(dsm);

    if (tid < 16) {   // nibble -> 4x f16 {0,1} LUT
        unsigned n = tid;
        uint2 e;
        e.x = ((n & 1) ? 0x3C00u : 0u) | ((n & 2) ? 0x3C000000u : 0u);
        e.y = ((n & 4) ? 0x3C00u : 0u) | ((n & 8) ? 0x3C000000u : 0u);
        *(uint2*)(dsm + SM_LUT + n * 8) = e;
    }

    // ---- build roles: row r (0..127), j-half q ----
    const int r = tid & 127;
    const int q = tid >> 7;
    const uint32_t PiPi = splat16(__half_as_ushort(g_PT [head * NN + i0 + r]));
    const uint32_t P2P2 = splat16(__half_as_ushort(g_P2T[head * NN + i0 + r]));
    const unsigned* maskrow = &g_adjb[(size_t)(i0 + r) * (NN / 32)];
    const uint32_t wstore = (uint32_t)SWZ((uint32_t)(r * 128 + q * 64)); // +k*16 swz-safe? no: apply SWZ per store

    // ---- mma roles ----
    const int m0   = wid * 16;
    const int arow = (lane & 7) + ((lane >> 3) & 1) * 8;
    const uint32_t a_base = (uint32_t)((m0 + arow) * 128 + (lane >> 4) * 16);
    const int brow = (lane & 7) + ((lane >> 3) & 1) * 8;
    const int bsel = (lane >> 4) & 1;

    float acc[8][4];
#pragma unroll
    for (int nt = 0; nt < 8; nt++)
#pragma unroll
        for (int c = 0; c < 4; c++) acc[nt][c] = 0.f;
    float zacc = 0.f;

    __syncthreads();   // LUT ready

    for (int t = 0; t < NCHUNK; t++) {
        const int j0 = t * BJ;
        const int b  = t & 1;
        const uint32_t wbufo = b ? SM_W1 : SM_W0;
        const uint32_t bbufo = b ? SM_B1 : SM_B0;

        // ---- build w tile (32 j per thread) + Z partial ----
        {
            const unsigned mask = maskrow[t * 2 + q];
            const uint4* Qp  = (const uint4*)&g_QT [head * NN + j0 + q * 32];
            const uint4* Q2p = (const uint4*)&g_Q2T[head * NN + j0 + q * 32];
#pragma unroll
            for (int k = 0; k < 4; k++) {
                uint4 qv  = Qp[k];
                uint4 q2v = Q2p[k];
                uint32_t w0 = hmax2_(hmul2_(PiPi, qv.x), hmul2_(P2P2, q2v.x));
                uint32_t w1 = hmax2_(hmul2_(PiPi, qv.y), hmul2_(P2P2, q2v.y));
                uint32_t w2 = hmax2_(hmul2_(PiPi, qv.z), hmul2_(P2P2, q2v.z));
                uint32_t w3 = hmax2_(hmul2_(PiPi, qv.w), hmul2_(P2P2, q2v.w));
                unsigned byte = (mask >> (k * 8)) & 0xFFu;
                uint2 lA = *(const uint2*)(dsm + SM_LUT + (byte & 15u) * 8);
                uint2 lB = *(const uint2*)(dsm + SM_LUT + (byte >> 4) * 8);
                w0 = hmul2_(w0, lA.x); w1 = hmul2_(w1, lA.y);
                w2 = hmul2_(w2, lB.x); w3 = hmul2_(w3, lB.y);
                uint32_t off = SWZ((uint32_t)(r * 128 + q * 64 + k * 16));
                *(uint4*)(dsm + wbufo + off) = make_uint4(w0, w1, w2, w3);
                // Z: halves sum <= 4 * ~max(w); f16-safe
                uint32_t t0 = hadd2_(hadd2_(w0, w1), hadd2_(w2, w3));
                float2 f = __half22float2(*(__half2*)&t0);
                zacc += f.x + f.y;
            }
        }
        // ---- stage B tile [64 j][64 d] f16 ----
#pragma unroll
        for (int u = 0; u < 2; u++) {
            int unit = tid + u * 256;
            int jrow = unit >> 3, seg = unit & 7;
            uint4 v = *(const uint4*)&g_hf[(size_t)(j0 + jrow) * FOUT + head * 64 + seg * 8];
            uint32_t off = SWZ((uint32_t)(jrow * 128 + seg * 16));
            *(uint4*)(dsm + bbufo + off) = v;
        }
        __syncthreads();

        // ---- mma phase ----
        const uint32_t wb = sb + wbufo;
        const uint32_t bb = sb + bbufo;
#pragma unroll
        for (int kk = 0; kk < 4; kk++) {
            uint32_t a0, a1, a2, a3;
            ldsm_x4(a0, a1, a2, a3, wb + SWZ(a_base + kk * 32));
#pragma unroll
            for (int ntp = 0; ntp < 4; ntp++) {
                uint32_t b0, b1, b2, b3;
                ldsm_x4_t(b0, b1, b2, b3,
                          bb + SWZ((uint32_t)(kk * 2048 + brow * 128 +
                                              (2 * ntp + bsel) * 16)));
                mma16816(acc[2 * ntp + 0], a0, a1, a2, a3, b0, b1);
                mma16816(acc[2 * ntp + 1], a0, a1, a2, a3, b2, b3);
            }
        }
        // no trailing sync: next build writes the other buffer; its last readers
        // (mma of t-1) are complete once any warp passes the sync above.
    }

    // ---- Z reduction: two halves per row ----
    ((float*)(dsm + SM_Z))[q * 128 + r] = zacc;
    __syncthreads();

    const float* zf = (const float*)(dsm + SM_Z);
    const int g4 = lane >> 2, t4 = lane & 3;
    const int row0 = m0 + g4, row1 = row0 + 8;
    const float iz0 = __frcp_rn(zf[row0] + zf[128 + row0]);
    const float iz1 = __frcp_rn(zf[row1] + zf[128 + row1]);

#pragma unroll
    for (int nt = 0; nt < 8; nt++) {
        const int col = nt * 8 + t4 * 2;
        float2 bv = *(const float2*)&bias[head * 64 + col];
        float2 o0, o1;
        o0.x = fmaf(acc[nt][0], iz0, bv.x);
        o0.y = fmaf(acc[nt][1], iz0, bv.y);
        o1.x = fmaf(acc[nt][2], iz1, bv.x);
        o1.y = fmaf(acc[nt][3], iz1, bv.y);
        *(float2*)&out[(size_t)(i0 + row0) * FOUT + head * 64 + col] = o0;
        *(float2*)&out[(size_t)(i0 + row1) * FOUT + head * 64 + col] = o1;
    }
}

// ---------------------------------------------------------------------------
extern "C" void kernel_launch(void* const* d_in, const int* in_sizes, int n_in,
                              void* d_out, int out_size) {
    const float* x     = (const float*)d_in[0];
    const int*   adj   = (const int*)  d_in[1];
    const float* W     = (const float*)d_in[2];
    const float* a_src = (const float*)d_in[3];
    const float* a_dst = (const float*)d_in[4];
    const float* bias  = (const float*)d_in[5];
    float* out = (float*)d_out;

    static int smem_set = 0;
    if (!smem_set) {
        cudaFuncSetAttribute(aggregate_kernel,
                             cudaFuncAttributeMaxDynamicSharedMemorySize, SM_TOTAL);
        smem_set = 1;
    }

    transform_kernel<<<dim3(NN / 64, FOUT / 64), 256>>>(x, W);
    attn_vec_kernel<<<(NN * HEADS) / 256, 256>>>(a_src, a_dst);
    pack_kernel<<<(NN * (NN / 32)) / 256, 256>>>(adj);
    aggregate_kernel<<<dim3(NN / BI, HEADS), 256, SM_TOTAL>>>(bias, out);
}

// round 7
// speedup vs baseline: 88.7667x; 1.0186x over previous
#include <cuda_runtime.h>
#include <cuda_fp16.h>
#include <cstdint>

// ============================================================================
// SpatialGAT on GB300 — round 7: register-fragment HMMA aggregation
//
// Stage 1: h = x @ W (fp32) -> g_h fp32 + g_hf f16
// Stage 2: P=exp(src),P2=exp(.2s),Q=exp(dst),Q2=exp(.2d)  f16 head-major
// Stage 3: pack adj -> bitmask g_adjb [N][N/32]
// Stage 4: per (i-tile 256, head): A fragments (w = bit * max(Pi*Qj,P2i*Q2j))
//          built DIRECTLY IN REGISTERS in mma layout; B tile (h f16) staged by
//          cp.async double buffer; Z via extra HMMA against constant ones.
// ============================================================================

#define NN      8192
#define FOUT    256
#define FIN     256
#define HEADS   4
#define NEG_SLOPE 0.2f
#define BI      256
#define BJ      64
#define NCHUNK  (NN / BJ)
#define NWORDS  (NN / 32)

__device__ float    g_h [NN * FOUT];
__device__ __half   g_hf[NN * FOUT];
__device__ __half   g_PT [HEADS * NN];
__device__ __half   g_P2T[HEADS * NN];
__device__ __half   g_QT [HEADS * NN];
__device__ __half   g_Q2T[HEADS * NN];
__device__ unsigned g_adjb[NN * NWORDS];

// ---------------------------------------------------------------------------
__device__ __forceinline__ uint32_t smem_u32(const void* p) {
    uint32_t a;
    asm("{ .reg .u64 t; cvta.to.shared.u64 t, %1; cvt.u32.u64 %0, t; }"
        : "=r"(a) : "l"(p));
    return a;
}
__device__ __forceinline__ uint32_t hmul2_(uint32_t a, uint32_t b) {
    uint32_t d; asm("mul.f16x2 %0, %1, %2;" : "=r"(d) : "r"(a), "r"(b)); return d;
}
__device__ __forceinline__ uint32_t hmax2_(uint32_t a, uint32_t b) {
    uint32_t d; asm("max.f16x2 %0, %1, %2;" : "=r"(d) : "r"(a), "r"(b)); return d;
}
__device__ __forceinline__ uint32_t splat16(unsigned short h) {
    uint32_t r; asm("mov.b32 %0, {%1, %1};" : "=r"(r) : "h"(h)); return r;
}
__device__ __forceinline__ uint32_t mask2(uint32_t bits) {
    // bits0 -> low f16 mask, bit1 -> high f16 mask
    return ((bits & 1u) ? 0x0000FFFFu : 0u) | ((bits & 2u) ? 0xFFFF0000u : 0u);
}
__device__ __forceinline__ void ldsm_x4_t(uint32_t& r0, uint32_t& r1, uint32_t& r2,
                                          uint32_t& r3, uint32_t addr) {
    asm volatile("ldmatrix.sync.aligned.m8n8.x4.trans.shared.b16 {%0,%1,%2,%3}, [%4];"
                 : "=r"(r0), "=r"(r1), "=r"(r2), "=r"(r3) : "r"(addr));
}
__device__ __forceinline__ void mma16816(float* c, uint32_t a0, uint32_t a1,
                                         uint32_t a2, uint32_t a3,
                                         uint32_t b0, uint32_t b1) {
    asm volatile(
        "mma.sync.aligned.m16n8k16.row.col.f32.f16.f16.f32 "
        "{%0,%1,%2,%3}, {%4,%5,%6,%7}, {%8,%9}, {%0,%1,%2,%3};"
        : "+f"(c[0]), "+f"(c[1]), "+f"(c[2]), "+f"(c[3])
        : "r"(a0), "r"(a1), "r"(a2), "r"(a3), "r"(b0), "r"(b1));
}
__device__ __forceinline__ void cp_async16(uint32_t dst, const void* src) {
    unsigned long long g;
    asm("cvta.to.global.u64 %0, %1;" : "=l"(g) : "l"(src));
    asm volatile("cp.async.ca.shared.global [%0], [%1], 16;" :: "r"(dst), "l"(g));
}
__device__ __forceinline__ void cp_commit() {
    asm volatile("cp.async.commit_group;" ::: "memory");
}
__device__ __forceinline__ void cp_wait_all() {
    asm volatile("cp.async.wait_group 0;" ::: "memory");
}
#define SWZ(off) ((off) ^ (((off) >> 3) & 0x70))

// ---------------------------------------------------------------------------
// Stage 1: h = x @ W (fp32 + f16 copy)
// ---------------------------------------------------------------------------
__global__ void __launch_bounds__(256) transform_kernel(const float* __restrict__ x,
                                                        const float* __restrict__ W) {
    __shared__ float xs[64][16];
    __shared__ float ws[16][64];
    const int tid = threadIdx.x;
    const int i0 = blockIdx.x * 64, j0 = blockIdx.y * 64;
    const int tx = tid & 15, ty = tid >> 4;

    float acc[4][4];
#pragma unroll
    for (int r = 0; r < 4; r++)
#pragma unroll
        for (int c = 0; c < 4; c++) acc[r][c] = 0.f;

    for (int k0 = 0; k0 < FIN; k0 += 16) {
        {
            int r = tid >> 2, c = (tid & 3) << 2;
            *(float4*)&xs[r][c] = *(const float4*)&x[(size_t)(i0 + r) * FIN + k0 + c];
        }
        {
            int l = tid << 2, c = l >> 6, j = l & 63;
            *(float4*)&ws[c][j] = *(const float4*)&W[(size_t)(k0 + c) * FOUT + j0 + j];
        }
        __syncthreads();
#pragma unroll
        for (int kk = 0; kk < 16; kk++) {
            float a[4];
#pragma unroll
            for (int r = 0; r < 4; r++) a[r] = xs[ty * 4 + r][kk];
            float4 bv = *(const float4*)&ws[kk][tx * 4];
#pragma unroll
            for (int r = 0; r < 4; r++) {
                acc[r][0] = fmaf(a[r], bv.x, acc[r][0]);
                acc[r][1] = fmaf(a[r], bv.y, acc[r][1]);
                acc[r][2] = fmaf(a[r], bv.z, acc[r][2]);
                acc[r][3] = fmaf(a[r], bv.w, acc[r][3]);
            }
        }
        __syncthreads();
    }
#pragma unroll
    for (int r = 0; r < 4; r++) {
        size_t o = (size_t)(i0 + ty * 4 + r) * FOUT + j0 + tx * 4;
        *(float4*)&g_h[o] = make_float4(acc[r][0], acc[r][1], acc[r][2], acc[r][3]);
        __half2 h01 = __floats2half2_rn(acc[r][0], acc[r][1]);
        __half2 h23 = __floats2half2_rn(acc[r][2], acc[r][3]);
        uint2 hv;
        hv.x = *(uint32_t*)&h01;
        hv.y = *(uint32_t*)&h23;
        *(uint2*)&g_hf[o] = hv;
    }
}

// ---------------------------------------------------------------------------
// Stage 2: exp tables (f16, head-major)
// ---------------------------------------------------------------------------
__global__ void __launch_bounds__(256) attn_vec_kernel(const float* __restrict__ a_src,
                                                       const float* __restrict__ a_dst) {
    int idx = blockIdx.x * blockDim.x + threadIdx.x;
    if (idx >= NN * HEADS) return;
    int n = idx >> 2, h = idx & 3;
    const float* hp = &g_h[(size_t)n * FOUT + h * 64];
    const float* as = &a_src[h * 64];
    const float* ad = &a_dst[h * 64];
    float s = 0.f, d = 0.f;
#pragma unroll 8
    for (int k = 0; k < 64; k++) {
        float v = hp[k];
        s = fmaf(v, as[k], s);
        d = fmaf(v, ad[k], d);
    }
    int o = h * NN + n;
    g_PT [o] = __float2half_rn(expf(s));
    g_P2T[o] = __float2half_rn(expf(NEG_SLOPE * s));
    g_QT [o] = __float2half_rn(expf(d));
    g_Q2T[o] = __float2half_rn(expf(NEG_SLOPE * d));
}

// ---------------------------------------------------------------------------
// Stage 3: pack adj -> bitmask
// ---------------------------------------------------------------------------
__global__ void __launch_bounds__(256) pack_kernel(const int* __restrict__ adj) {
    int word = blockIdx.x * 256 + threadIdx.x;
    const int4* p = (const int4*)&adj[(size_t)word * 32];
    unsigned m = 0;
#pragma unroll
    for (int k = 0; k < 8; k++) {
        int4 v = p[k];
        m |= (unsigned)(v.x != 0) << (4 * k + 0);
        m |= (unsigned)(v.y != 0) << (4 * k + 1);
        m |= (unsigned)(v.z != 0) << (4 * k + 2);
        m |= (unsigned)(v.w != 0) << (4 * k + 3);
    }
    g_adjb[word] = m;
}

// ---------------------------------------------------------------------------
// Stage 4: HMMA aggregation, in-register A build.
// dyn smem: B double buffer, 2 x 8KB.
// ---------------------------------------------------------------------------
extern __shared__ unsigned char dsm[];

__global__ void __launch_bounds__(256, 1)
aggregate_kernel(const float* __restrict__ bias, float* __restrict__ out) {
    const int tid  = threadIdx.x;
    const int lane = tid & 31;
    const int wid  = tid >> 5;
    const int head = blockIdx.y;
    const int i0   = blockIdx.x * BI;
    const uint32_t sb = smem_u32(dsm);

    // B staging role (cp.async): 2 x 16B per thread
    const int jr0 = tid >> 3, seg0 = (tid & 7);            // unit = tid
    const int jr1 = (tid + 256) >> 3, seg1 = (tid & 7);    // unit = tid+256
    const uint32_t bst0 = SWZ((uint32_t)(jr0 * 128 + seg0 * 16));
    const uint32_t bst1 = SWZ((uint32_t)(jr1 * 128 + seg1 * 16));

    // mma roles
    const int brow = (lane & 7) + ((lane >> 3) & 1) * 8;
    const int bsel = (lane >> 4) & 1;
    const int qrow = lane >> 2;          // row-in-tile base
    const int qcol = (lane & 3) * 2;     // col base within k16

    // per-thread rows: r4 = 0..3 -> offset {0,8,16,24}; mt = r4>>1
    int rows[4];
    uint32_t Ph[4], P2h[4];
#pragma unroll
    for (int r4 = 0; r4 < 4; r4++) {
        rows[r4] = wid * 32 + ((r4 >> 1) * 16) + ((r4 & 1) * 8) + qrow;
        int gi = head * NN + i0 + rows[r4];
        Ph[r4]  = splat16(__half_as_ushort(g_PT [gi]));
        P2h[r4] = splat16(__half_as_ushort(g_P2T[gi]));
    }

    float acc[2][8][4];
#pragma unroll
    for (int mt = 0; mt < 2; mt++)
#pragma unroll
        for (int nt = 0; nt < 8; nt++)
#pragma unroll
            for (int c = 0; c < 4; c++) acc[mt][nt][c] = 0.f;
    float zc[2][4] = {{0.f,0.f,0.f,0.f},{0.f,0.f,0.f,0.f}};
    const uint32_t ONES = 0x3C003C00u;

    // prologue: stage B(0), prefetch masks(0)
    {
        const __half* s0 = &g_hf[(size_t)(0 + jr0) * FOUT + head * 64 + seg0 * 8];
        const __half* s1 = &g_hf[(size_t)(0 + jr1) * FOUT + head * 64 + seg1 * 8];
        cp_async16(sb + bst0, s0);
        cp_async16(sb + bst1, s1);
        cp_commit();
    }
    uint2 mrow[4];
#pragma unroll
    for (int r4 = 0; r4 < 4; r4++)
        mrow[r4] = *(const uint2*)&g_adjb[(size_t)(i0 + rows[r4]) * NWORDS];

    const __half* Qbase  = &g_QT [head * NN];
    const __half* Q2base = &g_Q2T[head * NN];

    for (int t = 0; t < NCHUNK; t++) {
        const int b = t & 1;
        const int j0 = t * BJ;
        const uint32_t bbuf = sb + (b ? 8192u : 0u);

        cp_wait_all();
        __syncthreads();

        // prefetch B(t+1) into other buffer
        {
            const int tn = (t + 1 < NCHUNK) ? t + 1 : t;
            const int jn = tn * BJ;
            const uint32_t obuf = sb + (b ? 0u : 8192u);
            cp_async16(obuf + bst0, &g_hf[(size_t)(jn + jr0) * FOUT + head * 64 + seg0 * 8]);
            cp_async16(obuf + bst1, &g_hf[(size_t)(jn + jr1) * FOUT + head * 64 + seg1 * 8]);
            cp_commit();
        }
        // copy masks, prefetch next
        uint2 cm[4];
#pragma unroll
        for (int r4 = 0; r4 < 4; r4++) cm[r4] = mrow[r4];
        {
            const int tn = (t + 1 < NCHUNK) ? t + 1 : t;
#pragma unroll
            for (int r4 = 0; r4 < 4; r4++)
                mrow[r4] = *(const uint2*)&g_adjb[(size_t)(i0 + rows[r4]) * NWORDS + tn * 2];
        }

#pragma unroll
        for (int kk = 0; kk < 4; kk++) {
            // Q tables for this k16 block (L1-hot)
            const uint32_t* Qp  = (const uint32_t*)(Qbase  + j0 + kk * 16 + qcol);
            const uint32_t* Q2p = (const uint32_t*)(Q2base + j0 + kk * 16 + qcol);
            const uint32_t Qa = Qp[0],  Qb = Qp[4];
            const uint32_t Q2a = Q2p[0], Q2b = Q2p[4];
            const uint32_t sh = ((kk & 1) << 4) + qcol;

            uint32_t a[2][4];
#pragma unroll
            for (int r4 = 0; r4 < 4; r4++) {
                const uint32_t W = (kk & 2) ? cm[r4].y : cm[r4].x;
                const uint32_t ba = W >> sh;
                const uint32_t wa = hmax2_(hmul2_(Ph[r4], Qa), hmul2_(P2h[r4], Q2a)) & mask2(ba);
                const uint32_t wb = hmax2_(hmul2_(Ph[r4], Qb), hmul2_(P2h[r4], Q2b)) & mask2(ba >> 8);
                a[r4 >> 1][(r4 & 1)]     = wa;
                a[r4 >> 1][(r4 & 1) + 2] = wb;
            }
            // Z: ones-B mma (row sums), replicated across lane quads
            mma16816(zc[0], a[0][0], a[0][1], a[0][2], a[0][3], ONES, ONES);
            mma16816(zc[1], a[1][0], a[1][1], a[1][2], a[1][3], ONES, ONES);
            // B tiles + mma
#pragma unroll
            for (int ntp = 0; ntp < 4; ntp++) {
                uint32_t b0, b1, b2, b3;
                ldsm_x4_t(b0, b1, b2, b3,
                          bbuf + SWZ((uint32_t)(kk * 2048 + brow * 128 +
                                                (2 * ntp + bsel) * 16)));
                mma16816(acc[0][2 * ntp + 0], a[0][0], a[0][1], a[0][2], a[0][3], b0, b1);
                mma16816(acc[0][2 * ntp + 1], a[0][0], a[0][1], a[0][2], a[0][3], b2, b3);
                mma16816(acc[1][2 * ntp + 0], a[1][0], a[1][1], a[1][2], a[1][3], b0, b1);
                mma16816(acc[1][2 * ntp + 1], a[1][0], a[1][1], a[1][2], a[1][3], b2, b3);
            }
        }
    }

    // ---- epilogue: normalize + bias ----
#pragma unroll
    for (int mt = 0; mt < 2; mt++) {
        const float izlo = __frcp_rn(zc[mt][0]);
        const float izhi = __frcp_rn(zc[mt][2]);
        const int rlo = i0 + wid * 32 + mt * 16 + qrow;
#pragma unroll
        for (int nt = 0; nt < 8; nt++) {
            const int col = head * 64 + nt * 8 + qcol;
            const float2 bv = *(const float2*)&bias[col];
            float2 o0, o1;
            o0.x = fmaf(acc[mt][nt][0], izlo, bv.x);
            o0.y = fmaf(acc[mt][nt][1], izlo, bv.y);
            o1.x = fmaf(acc[mt][nt][2], izhi, bv.x);
            o1.y = fmaf(acc[mt][nt][3], izhi, bv.y);
            *(float2*)&out[(size_t)rlo * FOUT + col] = o0;
            *(float2*)&out[(size_t)(rlo + 8) * FOUT + col] = o1;
        }
    }
}

// ---------------------------------------------------------------------------
extern "C" void kernel_launch(void* const* d_in, const int* in_sizes, int n_in,
                              void* d_out, int out_size) {
    const float* x     = (const float*)d_in[0];
    const int*   adj   = (const int*)  d_in[1];
    const float* W     = (const float*)d_in[2];
    const float* a_src = (const float*)d_in[3];
    const float* a_dst = (const float*)d_in[4];
    const float* bias  = (const float*)d_in[5];
    float* out = (float*)d_out;

    transform_kernel<<<dim3(NN / 64, FOUT / 64), 256>>>(x, W);
    attn_vec_kernel<<<(NN * HEADS) / 256, 256>>>(a_src, a_dst);
    pack_kernel<<<(NN * NWORDS) / 256, 256>>>(adj);
    aggregate_kernel<<<dim3(NN / BI, HEADS), 256, 16384>>>(bias, out);
}

// round 8
// speedup vs baseline: 102.4956x; 1.1547x over previous
#include <cuda_runtime.h>
#include <cuda_fp16.h>
#include <cstdint>

// ============================================================================
// SpatialGAT on GB300 — round 8: occupancy-fixed register-fragment HMMA
//   BI=128, 8 warps x 16 rows, <=128 regs, 2 CTAs/SM (16 warps/SM).
//
// Stage 1: h = x @ W (fp32) -> g_h fp32 + g_hf f16
// Stage 2: P=exp(src),P2=exp(.2s),Q=exp(dst),Q2=exp(.2d)  f16 head-major
// Stage 3: pack adj -> bitmask g_adjb [N][N/32]
// Stage 4: per (i-tile 128, head): A fragments (w = bit * max(Pi*Qj,P2i*Q2j))
//          built in registers in mma layout; B via cp.async double buffer;
//          Z via extra HMMA against ones.
// ============================================================================

#define NN      8192
#define FOUT    256
#define FIN     256
#define HEADS   4
#define NEG_SLOPE 0.2f
#define BI      128
#define BJ      64
#define NCHUNK  (NN / BJ)
#define NWORDS  (NN / 32)

__device__ float    g_h [NN * FOUT];
__device__ __half   g_hf[NN * FOUT];
__device__ __half   g_PT [HEADS * NN];
__device__ __half   g_P2T[HEADS * NN];
__device__ __half   g_QT [HEADS * NN];
__device__ __half   g_Q2T[HEADS * NN];
__device__ unsigned g_adjb[NN * NWORDS];

// ---------------------------------------------------------------------------
__device__ __forceinline__ uint32_t smem_u32(const void* p) {
    uint32_t a;
    asm("{ .reg .u64 t; cvta.to.shared.u64 t, %1; cvt.u32.u64 %0, t; }"
        : "=r"(a) : "l"(p));
    return a;
}
__device__ __forceinline__ uint32_t hmul2_(uint32_t a, uint32_t b) {
    uint32_t d; asm("mul.f16x2 %0, %1, %2;" : "=r"(d) : "r"(a), "r"(b)); return d;
}
__device__ __forceinline__ uint32_t hmax2_(uint32_t a, uint32_t b) {
    uint32_t d; asm("max.f16x2 %0, %1, %2;" : "=r"(d) : "r"(a), "r"(b)); return d;
}
__device__ __forceinline__ uint32_t splat16(unsigned short h) {
    uint32_t r; asm("mov.b32 %0, {%1, %1};" : "=r"(r) : "h"(h)); return r;
}
__device__ __forceinline__ uint32_t mask2(uint32_t bits) {
    return ((bits & 1u) ? 0x0000FFFFu : 0u) | ((bits & 2u) ? 0xFFFF0000u : 0u);
}
__device__ __forceinline__ void ldsm_x4_t(uint32_t& r0, uint32_t& r1, uint32_t& r2,
                                          uint32_t& r3, uint32_t addr) {
    asm volatile("ldmatrix.sync.aligned.m8n8.x4.trans.shared.b16 {%0,%1,%2,%3}, [%4];"
                 : "=r"(r0), "=r"(r1), "=r"(r2), "=r"(r3) : "r"(addr));
}
__device__ __forceinline__ void mma16816(float* c, uint32_t a0, uint32_t a1,
                                         uint32_t a2, uint32_t a3,
                                         uint32_t b0, uint32_t b1) {
    asm volatile(
        "mma.sync.aligned.m16n8k16.row.col.f32.f16.f16.f32 "
        "{%0,%1,%2,%3}, {%4,%5,%6,%7}, {%8,%9}, {%0,%1,%2,%3};"
        : "+f"(c[0]), "+f"(c[1]), "+f"(c[2]), "+f"(c[3])
        : "r"(a0), "r"(a1), "r"(a2), "r"(a3), "r"(b0), "r"(b1));
}
__device__ __forceinline__ void cp_async16(uint32_t dst, const void* src) {
    unsigned long long g;
    asm("cvta.to.global.u64 %0, %1;" : "=l"(g) : "l"(src));
    asm volatile("cp.async.ca.shared.global [%0], [%1], 16;" :: "r"(dst), "l"(g));
}
__device__ __forceinline__ void cp_commit() {
    asm volatile("cp.async.commit_group;" ::: "memory");
}
__device__ __forceinline__ void cp_wait_all() {
    asm volatile("cp.async.wait_group 0;" ::: "memory");
}
#define SWZ(off) ((off) ^ (((off) >> 3) & 0x70))

// ---------------------------------------------------------------------------
// Stage 1: h = x @ W (fp32 + f16 copy)
// ---------------------------------------------------------------------------
__global__ void __launch_bounds__(256) transform_kernel(const float* __restrict__ x,
                                                        const float* __restrict__ W) {
    __shared__ float xs[64][16];
    __shared__ float ws[16][64];
    const int tid = threadIdx.x;
    const int i0 = blockIdx.x * 64, j0 = blockIdx.y * 64;
    const int tx = tid & 15, ty = tid >> 4;

    float acc[4][4];
#pragma unroll
    for (int r = 0; r < 4; r++)
#pragma unroll
        for (int c = 0; c < 4; c++) acc[r][c] = 0.f;

    for (int k0 = 0; k0 < FIN; k0 += 16) {
        {
            int r = tid >> 2, c = (tid & 3) << 2;
            *(float4*)&xs[r][c] = *(const float4*)&x[(size_t)(i0 + r) * FIN + k0 + c];
        }
        {
            int l = tid << 2, c = l >> 6, j = l & 63;
            *(float4*)&ws[c][j] = *(const float4*)&W[(size_t)(k0 + c) * FOUT + j0 + j];
        }
        __syncthreads();
#pragma unroll
        for (int kk = 0; kk < 16; kk++) {
            float a[4];
#pragma unroll
            for (int r = 0; r < 4; r++) a[r] = xs[ty * 4 + r][kk];
            float4 bv = *(const float4*)&ws[kk][tx * 4];
#pragma unroll
            for (int r = 0; r < 4; r++) {
                acc[r][0] = fmaf(a[r], bv.x, acc[r][0]);
                acc[r][1] = fmaf(a[r], bv.y, acc[r][1]);
                acc[r][2] = fmaf(a[r], bv.z, acc[r][2]);
                acc[r][3] = fmaf(a[r], bv.w, acc[r][3]);
            }
        }
        __syncthreads();
    }
#pragma unroll
    for (int r = 0; r < 4; r++) {
        size_t o = (size_t)(i0 + ty * 4 + r) * FOUT + j0 + tx * 4;
        *(float4*)&g_h[o] = make_float4(acc[r][0], acc[r][1], acc[r][2], acc[r][3]);
        __half2 h01 = __floats2half2_rn(acc[r][0], acc[r][1]);
        __half2 h23 = __floats2half2_rn(acc[r][2], acc[r][3]);
        uint2 hv;
        hv.x = *(uint32_t*)&h01;
        hv.y = *(uint32_t*)&h23;
        *(uint2*)&g_hf[o] = hv;
    }
}

// ---------------------------------------------------------------------------
// Stage 2: exp tables (f16, head-major)
// ---------------------------------------------------------------------------
__global__ void __launch_bounds__(256) attn_vec_kernel(const float* __restrict__ a_src,
                                                       const float* __restrict__ a_dst) {
    int idx = blockIdx.x * blockDim.x + threadIdx.x;
    if (idx >= NN * HEADS) return;
    int n = idx >> 2, h = idx & 3;
    const float* hp = &g_h[(size_t)n * FOUT + h * 64];
    const float* as = &a_src[h * 64];
    const float* ad = &a_dst[h * 64];
    float s = 0.f, d = 0.f;
#pragma unroll 8
    for (int k = 0; k < 64; k++) {
        float v = hp[k];
        s = fmaf(v, as[k], s);
        d = fmaf(v, ad[k], d);
    }
    int o = h * NN + n;
    g_PT [o] = __float2half_rn(expf(s));
    g_P2T[o] = __float2half_rn(expf(NEG_SLOPE * s));
    g_QT [o] = __float2half_rn(expf(d));
    g_Q2T[o] = __float2half_rn(expf(NEG_SLOPE * d));
}

// ---------------------------------------------------------------------------
// Stage 3: pack adj -> bitmask
// ---------------------------------------------------------------------------
__global__ void __launch_bounds__(256) pack_kernel(const int* __restrict__ adj) {
    int word = blockIdx.x * 256 + threadIdx.x;
    const int4* p = (const int4*)&adj[(size_t)word * 32];
    unsigned m = 0;
#pragma unroll
    for (int k = 0; k < 8; k++) {
        int4 v = p[k];
        m |= (unsigned)(v.x != 0) << (4 * k + 0);
        m |= (unsigned)(v.y != 0) << (4 * k + 1);
        m |= (unsigned)(v.z != 0) << (4 * k + 2);
        m |= (unsigned)(v.w != 0) << (4 * k + 3);
    }
    g_adjb[word] = m;
}

// ---------------------------------------------------------------------------
// Stage 4: HMMA aggregation, in-register A build, 16 rows/warp, 2 CTAs/SM.
// dyn smem: B double buffer, 2 x 8KB.
// ---------------------------------------------------------------------------
extern __shared__ unsigned char dsm[];

__global__ void __launch_bounds__(256, 2)
aggregate_kernel(const float* __restrict__ bias, float* __restrict__ out) {
    const int tid  = threadIdx.x;
    const int lane = tid & 31;
    const int wid  = tid >> 5;
    const int head = blockIdx.y;
    const int i0   = blockIdx.x * BI;
    const uint32_t sb = smem_u32(dsm);

    // B staging (cp.async): B tile 64x64 f16 = 8KB, 256 thr -> 2 x 16B each
    const int jr0 = tid >> 3, seg0 = (tid & 7);
    const int jr1 = (tid + 256) >> 3, seg1 = (tid & 7);
    const uint32_t bst0 = SWZ((uint32_t)(jr0 * 128 + seg0 * 16));
    const uint32_t bst1 = SWZ((uint32_t)(jr1 * 128 + seg1 * 16));

    // mma roles
    const int brow = (lane & 7) + ((lane >> 3) & 1) * 8;
    const int bsel = (lane >> 4) & 1;
    const int qrow = lane >> 2;
    const int qcol = (lane & 3) * 2;

    // this warp's 16-row m-tile; thread rows qrow, qrow+8
    int rows[2];
    uint32_t Ph[2], P2h[2];
#pragma unroll
    for (int r4 = 0; r4 < 2; r4++) {
        rows[r4] = wid * 16 + r4 * 8 + qrow;
        int gi = head * NN + i0 + rows[r4];
        Ph[r4]  = splat16(__half_as_ushort(g_PT [gi]));
        P2h[r4] = splat16(__half_as_ushort(g_P2T[gi]));
    }

    float acc[8][4];
#pragma unroll
    for (int nt = 0; nt < 8; nt++)
#pragma unroll
        for (int c = 0; c < 4; c++) acc[nt][c] = 0.f;
    float zc[4] = {0.f, 0.f, 0.f, 0.f};
    const uint32_t ONES = 0x3C003C00u;

    // prologue: stage B(0), prefetch masks(0)
    cp_async16(sb + bst0, &g_hf[(size_t)jr0 * FOUT + head * 64 + seg0 * 8]);
    cp_async16(sb + bst1, &g_hf[(size_t)jr1 * FOUT + head * 64 + seg1 * 8]);
    cp_commit();

    uint2 mrow[2];
#pragma unroll
    for (int r4 = 0; r4 < 2; r4++)
        mrow[r4] = *(const uint2*)&g_adjb[(size_t)(i0 + rows[r4]) * NWORDS];

    const __half* Qbase  = &g_QT [head * NN];
    const __half* Q2base = &g_Q2T[head * NN];

    for (int t = 0; t < NCHUNK; t++) {
        const int b = t & 1;
        const int j0 = t * BJ;
        const uint32_t bbuf = sb + (b ? 8192u : 0u);

        cp_wait_all();
        __syncthreads();

        // prefetch B(t+1)
        {
            const int tn = (t + 1 < NCHUNK) ? t + 1 : t;
            const int jn = tn * BJ;
            const uint32_t obuf = sb + (b ? 0u : 8192u);
            cp_async16(obuf + bst0, &g_hf[(size_t)(jn + jr0) * FOUT + head * 64 + seg0 * 8]);
            cp_async16(obuf + bst1, &g_hf[(size_t)(jn + jr1) * FOUT + head * 64 + seg1 * 8]);
            cp_commit();
        }
        // copy masks, prefetch next
        uint2 cm[2];
#pragma unroll
        for (int r4 = 0; r4 < 2; r4++) cm[r4] = mrow[r4];
        {
            const int tn = (t + 1 < NCHUNK) ? t + 1 : t;
#pragma unroll
            for (int r4 = 0; r4 < 2; r4++)
                mrow[r4] = *(const uint2*)&g_adjb[(size_t)(i0 + rows[r4]) * NWORDS + tn * 2];
        }

#pragma unroll
        for (int kk = 0; kk < 4; kk++) {
            const uint32_t* Qp  = (const uint32_t*)(Qbase  + j0 + kk * 16 + qcol);
            const uint32_t* Q2p = (const uint32_t*)(Q2base + j0 + kk * 16 + qcol);
            const uint32_t Qa = Qp[0],  Qb = Qp[4];
            const uint32_t Q2a = Q2p[0], Q2b = Q2p[4];
            const uint32_t sh = ((kk & 1) << 4) + qcol;

            uint32_t a[4];
#pragma unroll
            for (int r4 = 0; r4 < 2; r4++) {
                const uint32_t Wm = (kk & 2) ? cm[r4].y : cm[r4].x;
                const uint32_t ba = Wm >> sh;
                a[r4]     = hmax2_(hmul2_(Ph[r4], Qa), hmul2_(P2h[r4], Q2a)) & mask2(ba);
                a[r4 + 2] = hmax2_(hmul2_(Ph[r4], Qb), hmul2_(P2h[r4], Q2b)) & mask2(ba >> 8);
            }
            // Z row sums via ones-B mma
            mma16816(zc, a[0], a[1], a[2], a[3], ONES, ONES);
            // B tiles + mma
#pragma unroll
            for (int ntp = 0; ntp < 4; ntp++) {
                uint32_t b0, b1, b2, b3;
                ldsm_x4_t(b0, b1, b2, b3,
                          bbuf + SWZ((uint32_t)(kk * 2048 + brow * 128 +
                                                (2 * ntp + bsel) * 16)));
                mma16816(acc[2 * ntp + 0], a[0], a[1], a[2], a[3], b0, b1);
                mma16816(acc[2 * ntp + 1], a[0], a[1], a[2], a[3], b2, b3);
            }
        }
    }

    // ---- epilogue: normalize + bias ----
    const float izlo = __frcp_rn(zc[0]);
    const float izhi = __frcp_rn(zc[2]);
    const int rlo = i0 + wid * 16 + qrow;
#pragma unroll
    for (int nt = 0; nt < 8; nt++) {
        const int col = head * 64 + nt * 8 + qcol;
        const float2 bv = *(const float2*)&bias[col];
        float2 o0, o1;
        o0.x = fmaf(acc[nt][0], izlo, bv.x);
        o0.y = fmaf(acc[nt][1], izlo, bv.y);
        o1.x = fmaf(acc[nt][2], izhi, bv.x);
        o1.y = fmaf(acc[nt][3], izhi, bv.y);
        *(float2*)&out[(size_t)rlo * FOUT + col] = o0;
        *(float2*)&out[(size_t)(rlo + 8) * FOUT + col] = o1;
    }
}

// ---------------------------------------------------------------------------
extern "C" void kernel_launch(void* const* d_in, const int* in_sizes, int n_in,
                              void* d_out, int out_size) {
    const float* x     = (const float*)d_in[0];
    const int*   adj   = (const int*)  d_in[1];
    const float* W     = (const float*)d_in[2];
    const float* a_src = (const float*)d_in[3];
    const float* a_dst = (const float*)d_in[4];
    const float* bias  = (const float*)d_in[5];
    float* out = (float*)d_out;

    transform_kernel<<<dim3(NN / 64, FOUT / 64), 256>>>(x, W);
    attn_vec_kernel<<<(NN * HEADS) / 256, 256>>>(a_src, a_dst);
    pack_kernel<<<(NN * NWORDS) / 256, 256>>>(adj);
    aggregate_kernel<<<dim3(NN / BI, HEADS), 256, 16384>>>(bias, out);
}

// round 9
// speedup vs baseline: 121.3311x; 1.1838x over previous
#include <cuda_runtime.h>
#include <cuda_fp16.h>
#include <cstdint>

// ============================================================================
// SpatialGAT on GB300 — round 9: HMMA everywhere, BJ=128, swizzled Q tables
//
// Stage 0: cast x, W -> f16 (g_xf, g_Wf)
// Stage 1: h = x @ W via mma.sync f16 -> g_hf (f16 only)
// Stage 2: P/P2 tables (head-major) + Q/Q2 tables in kk-swizzled layout
// Stage 3: pack adj -> bitmask
// Stage 4: aggregation: A-fragments (w = bit * max(Pi*Qj,P2i*Q2j)) in regs,
//          B via cp.async double buffer (128x64 f16 tiles), Z via ones-mma.
// ============================================================================

#define NN      8192
#define FOUT    256
#define FIN     256
#define HEADS   4
#define NEG_SLOPE 0.2f
#define BI      128
#define BJ      128
#define NCHUNK  (NN / BJ)      // 64
#define NWORDS  (NN / 32)
#define NBLK64  (NN / 64)      // 128

__device__ __half   g_xf[NN * FIN];
__device__ __half   g_Wf[FIN * FOUT];
__device__ __half   g_hf[NN * FOUT];
__device__ __half   g_PT [HEADS * NN];
__device__ __half   g_P2T[HEADS * NN];
// swizzled Q tables: [head][blk64][m(0..7)][kk(0..3)] u32 (= f16 pair)
__device__ uint32_t g_Qsw [HEADS * NBLK64 * 32];
__device__ uint32_t g_Q2sw[HEADS * NBLK64 * 32];
__device__ unsigned g_adjb[NN * NWORDS];

// ---------------------------------------------------------------------------
__device__ __forceinline__ uint32_t smem_u32(const void* p) {
    uint32_t a;
    asm("{ .reg .u64 t; cvta.to.shared.u64 t, %1; cvt.u32.u64 %0, t; }"
        : "=r"(a) : "l"(p));
    return a;
}
__device__ __forceinline__ uint32_t hmul2_(uint32_t a, uint32_t b) {
    uint32_t d; asm("mul.f16x2 %0, %1, %2;" : "=r"(d) : "r"(a), "r"(b)); return d;
}
__device__ __forceinline__ uint32_t hmax2_(uint32_t a, uint32_t b) {
    uint32_t d; asm("max.f16x2 %0, %1, %2;" : "=r"(d) : "r"(a), "r"(b)); return d;
}
__device__ __forceinline__ uint32_t splat16(unsigned short h) {
    uint32_t r; asm("mov.b32 %0, {%1, %1};" : "=r"(r) : "h"(h)); return r;
}
__device__ __forceinline__ uint32_t mask2(uint32_t bits) {
    return ((bits & 1u) ? 0x0000FFFFu : 0u) | ((bits & 2u) ? 0xFFFF0000u : 0u);
}
__device__ __forceinline__ void ldsm_x4(uint32_t& r0, uint32_t& r1, uint32_t& r2,
                                        uint32_t& r3, uint32_t addr) {
    asm volatile("ldmatrix.sync.aligned.m8n8.x4.shared.b16 {%0,%1,%2,%3}, [%4];"
                 : "=r"(r0), "=r"(r1), "=r"(r2), "=r"(r3) : "r"(addr));
}
__device__ __forceinline__ void ldsm_x4_t(uint32_t& r0, uint32_t& r1, uint32_t& r2,
                                          uint32_t& r3, uint32_t addr) {
    asm volatile("ldmatrix.sync.aligned.m8n8.x4.trans.shared.b16 {%0,%1,%2,%3}, [%4];"
                 : "=r"(r0), "=r"(r1), "=r"(r2), "=r"(r3) : "r"(addr));
}
__device__ __forceinline__ void mma16816(float* c, uint32_t a0, uint32_t a1,
                                         uint32_t a2, uint32_t a3,
                                         uint32_t b0, uint32_t b1) {
    asm volatile(
        "mma.sync.aligned.m16n8k16.row.col.f32.f16.f16.f32 "
        "{%0,%1,%2,%3}, {%4,%5,%6,%7}, {%8,%9}, {%0,%1,%2,%3};"
        : "+f"(c[0]), "+f"(c[1]), "+f"(c[2]), "+f"(c[3])
        : "r"(a0), "r"(a1), "r"(a2), "r"(a3), "r"(b0), "r"(b1));
}
__device__ __forceinline__ void cp_async16(uint32_t dst, const void* src) {
    unsigned long long g;
    asm("cvta.to.global.u64 %0, %1;" : "=l"(g) : "l"(src));
    asm volatile("cp.async.ca.shared.global [%0], [%1], 16;" :: "r"(dst), "l"(g));
}
__device__ __forceinline__ void cp_commit() {
    asm volatile("cp.async.commit_group;" ::: "memory");
}
__device__ __forceinline__ void cp_wait_all() {
    asm volatile("cp.async.wait_group 0;" ::: "memory");
}
#define SWZ(off) ((off) ^ (((off) >> 3) & 0x70))

// ---------------------------------------------------------------------------
// Stage 0: cast x and W to f16
// ---------------------------------------------------------------------------
#define X4   (NN * FIN / 4)       // 524288
#define W4   (FIN * FOUT / 4)     // 16384
__global__ void __launch_bounds__(256) cast_kernel(const float* __restrict__ x,
                                                   const float* __restrict__ W) {
    int u = blockIdx.x * 256 + threadIdx.x;
    if (u < X4) {
        float4 v = ((const float4*)x)[u];
        __half2 a = __floats2half2_rn(v.x, v.y);
        __half2 b = __floats2half2_rn(v.z, v.w);
        uint2 o; o.x = *(uint32_t*)&a; o.y = *(uint32_t*)&b;
        ((uint2*)g_xf)[u] = o;
    } else if (u < X4 + W4) {
        int w = u - X4;
        float4 v = ((const float4*)W)[w];
        __half2 a = __floats2half2_rn(v.x, v.y);
        __half2 b = __floats2half2_rn(v.z, v.w);
        uint2 o; o.x = *(uint32_t*)&a; o.y = *(uint32_t*)&b;
        ((uint2*)g_Wf)[w] = o;
    }
}

// ---------------------------------------------------------------------------
// Stage 1: h = x @ W via HMMA. CTA: 128 rows x 64 cols, 8 warps x 16 rows.
// ---------------------------------------------------------------------------
__global__ void __launch_bounds__(256) transform_kernel() {
    __shared__ __align__(16) unsigned char ts[16384 + 8192];  // xs 16KB, ws 8KB
    const uint32_t sbx = smem_u32(ts);
    const uint32_t sbw = sbx + 16384;
    const int tid = threadIdx.x;
    const int lane = tid & 31, wid = tid >> 5;
    const int i0 = blockIdx.x * 128, n0 = blockIdx.y * 64;

    const int arow = (lane & 7) + ((lane >> 3) & 1) * 8;
    const uint32_t a_base = (uint32_t)((wid * 16 + arow) * 128 + (lane >> 4) * 16);
    const int brow = (lane & 7) + ((lane >> 3) & 1) * 8;
    const int bsel = (lane >> 4) & 1;
    const int qrow = lane >> 2, qcol = (lane & 3) * 2;

    float acc[8][4];
#pragma unroll
    for (int nt = 0; nt < 8; nt++)
#pragma unroll
        for (int c = 0; c < 4; c++) acc[nt][c] = 0.f;

    for (int kc = 0; kc < 4; kc++) {
        const int k0 = kc * 64;
        // stage x tile [128][64] f16 (4 x 16B per thread)
#pragma unroll
        for (int u = 0; u < 4; u++) {
            int unit = tid + u * 256;
            int row = unit >> 3, seg = unit & 7;
            uint4 v = *(const uint4*)&g_xf[(size_t)(i0 + row) * FIN + k0 + seg * 8];
            *(uint4*)(ts + SWZ((uint32_t)(row * 128 + seg * 16))) = v;
        }
        // stage W tile [64][64] f16 (2 x 16B per thread)
#pragma unroll
        for (int u = 0; u < 2; u++) {
            int unit = tid + u * 256;
            int row = unit >> 3, seg = unit & 7;
            uint4 v = *(const uint4*)&g_Wf[(size_t)(k0 + row) * FOUT + n0 + seg * 8];
            *(uint4*)(ts + 16384 + SWZ((uint32_t)(row * 128 + seg * 16))) = v;
        }
        __syncthreads();
#pragma unroll
        for (int kk = 0; kk < 4; kk++) {
            uint32_t a0, a1, a2, a3;
            ldsm_x4(a0, a1, a2, a3, sbx + SWZ(a_base + kk * 32));
#pragma unroll
            for (int ntp = 0; ntp < 4; ntp++) {
                uint32_t b0, b1, b2, b3;
                ldsm_x4_t(b0, b1, b2, b3,
                          sbw + SWZ((uint32_t)(kk * 2048 + brow * 128 +
                                               (2 * ntp + bsel) * 16)));
                mma16816(acc[2 * ntp + 0], a0, a1, a2, a3, b0, b1);
                mma16816(acc[2 * ntp + 1], a0, a1, a2, a3, b2, b3);
            }
        }
        __syncthreads();
    }
    // epilogue -> g_hf f16
    const int rlo = i0 + wid * 16 + qrow;
#pragma unroll
    for (int nt = 0; nt < 8; nt++) {
        const int col = n0 + nt * 8 + qcol;
        __half2 lo = __floats2half2_rn(acc[nt][0], acc[nt][1]);
        __half2 hi = __floats2half2_rn(acc[nt][2], acc[nt][3]);
        *(uint32_t*)&g_hf[(size_t)rlo * FOUT + col] = *(uint32_t*)&lo;
        *(uint32_t*)&g_hf[(size_t)(rlo + 8) * FOUT + col] = *(uint32_t*)&hi;
    }
}

// ---------------------------------------------------------------------------
// Stage 2: exp tables; P head-major, Q in kk-swizzled layout
// ---------------------------------------------------------------------------
__global__ void __launch_bounds__(256) attn_vec_kernel(const float* __restrict__ a_src,
                                                       const float* __restrict__ a_dst) {
    int idx = blockIdx.x * blockDim.x + threadIdx.x;
    if (idx >= NN * HEADS) return;
    int n = idx >> 2, h = idx & 3;
    const __half2* hp = (const __half2*)&g_hf[(size_t)n * FOUT + h * 64];
    const float* as = &a_src[h * 64];
    const float* ad = &a_dst[h * 64];
    float s = 0.f, d = 0.f;
#pragma unroll 8
    for (int k = 0; k < 32; k++) {
        float2 v = __half22float2(hp[k]);
        s = fmaf(v.x, as[2 * k], s);     s = fmaf(v.y, as[2 * k + 1], s);
        d = fmaf(v.x, ad[2 * k], d);     d = fmaf(v.y, ad[2 * k + 1], d);
    }
    int o = h * NN + n;
    g_PT [o] = __float2half_rn(expf(s));
    g_P2T[o] = __float2half_rn(expf(NEG_SLOPE * s));
    // swizzled Q write: j = blk*64 + kk*16 + within
    int blk = n >> 6, c = n & 63;
    int kk = c >> 4, within = c & 15;
    int m = within >> 1, hs = within & 1;
    size_t widx = ((size_t)(h * NBLK64 + blk) * 32 + m * 4 + kk) * 2 + hs;
    ((__half*)g_Qsw )[widx] = __float2half_rn(expf(d));
    ((__half*)g_Q2sw)[widx] = __float2half_rn(expf(NEG_SLOPE * d));
}

// ---------------------------------------------------------------------------
// Stage 3: pack adj -> bitmask
// ---------------------------------------------------------------------------
__global__ void __launch_bounds__(256) pack_kernel(const int* __restrict__ adj) {
    int word = blockIdx.x * 256 + threadIdx.x;
    const int4* p = (const int4*)&adj[(size_t)word * 32];
    unsigned m = 0;
#pragma unroll
    for (int k = 0; k < 8; k++) {
        int4 v = p[k];
        m |= (unsigned)(v.x != 0) << (4 * k + 0);
        m |= (unsigned)(v.y != 0) << (4 * k + 1);
        m |= (unsigned)(v.z != 0) << (4 * k + 2);
        m |= (unsigned)(v.w != 0) << (4 * k + 3);
    }
    g_adjb[word] = m;
}

// ---------------------------------------------------------------------------
// Stage 4: HMMA aggregation. BJ=128, B double buffer 2 x 16KB.
// ---------------------------------------------------------------------------
extern __shared__ unsigned char dsm[];

__global__ void __launch_bounds__(256, 2)
aggregate_kernel(const float* __restrict__ bias, float* __restrict__ out) {
    const int tid  = threadIdx.x;
    const int lane = tid & 31;
    const int wid  = tid >> 5;
    const int head = blockIdx.y;
    const int i0   = blockIdx.x * BI;
    const uint32_t sb = smem_u32(dsm);

    // B staging: tile 128x64 f16 = 16KB -> 4 x 16B per thread
    uint32_t bst[4];
    int jr[4], sg[4];
#pragma unroll
    for (int u = 0; u < 4; u++) {
        int unit = tid + u * 256;
        jr[u] = unit >> 3; sg[u] = unit & 7;
        bst[u] = SWZ((uint32_t)(jr[u] * 128 + sg[u] * 16));
    }

    const int brow = (lane & 7) + ((lane >> 3) & 1) * 8;
    const int bsel = (lane >> 4) & 1;
    const int qrow = lane >> 2;
    const int qcol = (lane & 3) * 2;

    int rows[2];
    uint32_t Ph[2], P2h[2];
#pragma unroll
    for (int r4 = 0; r4 < 2; r4++) {
        rows[r4] = wid * 16 + r4 * 8 + qrow;
        int gi = head * NN + i0 + rows[r4];
        Ph[r4]  = splat16(__half_as_ushort(g_PT [gi]));
        P2h[r4] = splat16(__half_as_ushort(g_P2T[gi]));
    }

    float acc[8][4];
#pragma unroll
    for (int nt = 0; nt < 8; nt++)
#pragma unroll
        for (int c = 0; c < 4; c++) acc[nt][c] = 0.f;
    float zc[4] = {0.f, 0.f, 0.f, 0.f};
    const uint32_t ONES = 0x3C003C00u;

    // prologue: stage B(0), masks(0)
#pragma unroll
    for (int u = 0; u < 4; u++)
        cp_async16(sb + bst[u], &g_hf[(size_t)jr[u] * FOUT + head * 64 + sg[u] * 8]);
    cp_commit();

    uint4 mrow[2];
#pragma unroll
    for (int r4 = 0; r4 < 2; r4++)
        mrow[r4] = *(const uint4*)&g_adjb[(size_t)(i0 + rows[r4]) * NWORDS];

    const uint32_t* Qsw  = &g_Qsw [head * NBLK64 * 32];
    const uint32_t* Q2sw = &g_Q2sw[head * NBLK64 * 32];
    const int moff = (lane & 3) * 4;

    for (int t = 0; t < NCHUNK; t++) {
        const int b = t & 1;
        const int j0 = t * BJ;
        const uint32_t bbuf = sb + (b ? 16384u : 0u);

        cp_wait_all();
        __syncthreads();

        // prefetch B(t+1)
        {
            const int tn = (t + 1 < NCHUNK) ? t + 1 : t;
            const int jn = tn * BJ;
            const uint32_t obuf = sb + (b ? 0u : 16384u);
#pragma unroll
            for (int u = 0; u < 4; u++)
                cp_async16(obuf + bst[u],
                           &g_hf[(size_t)(jn + jr[u]) * FOUT + head * 64 + sg[u] * 8]);
            cp_commit();
        }
        // current masks; prefetch next
        uint32_t cm[2][4];
#pragma unroll
        for (int r4 = 0; r4 < 2; r4++) {
            cm[r4][0] = mrow[r4].x; cm[r4][1] = mrow[r4].y;
            cm[r4][2] = mrow[r4].z; cm[r4][3] = mrow[r4].w;
        }
        {
            const int tn = (t + 1 < NCHUNK) ? t + 1 : t;
#pragma unroll
            for (int r4 = 0; r4 < 2; r4++)
                mrow[r4] = *(const uint4*)&g_adjb[(size_t)(i0 + rows[r4]) * NWORDS + tn * 4];
        }

#pragma unroll
        for (int b64 = 0; b64 < 2; b64++) {
            const int base = ((j0 >> 6) + b64) * 32;
            const uint4 Qa4  = *(const uint4*)&Qsw [base + moff];
            const uint4 Qb4  = *(const uint4*)&Qsw [base + 16 + moff];
            const uint4 Q2a4 = *(const uint4*)&Q2sw[base + moff];
            const uint4 Q2b4 = *(const uint4*)&Q2sw[base + 16 + moff];
            uint32_t QaA[4]  = {Qa4.x, Qa4.y, Qa4.z, Qa4.w};
            uint32_t QbA[4]  = {Qb4.x, Qb4.y, Qb4.z, Qb4.w};
            uint32_t Q2aA[4] = {Q2a4.x, Q2a4.y, Q2a4.z, Q2a4.w};
            uint32_t Q2bA[4] = {Q2b4.x, Q2b4.y, Q2b4.z, Q2b4.w};

#pragma unroll
            for (int k4 = 0; k4 < 4; k4++) {
                const int kk = b64 * 4 + k4;
                const uint32_t Qa = QaA[k4], Qb = QbA[k4];
                const uint32_t Q2a = Q2aA[k4], Q2b = Q2bA[k4];
                const uint32_t sh = ((kk & 1) << 4) + qcol;

                uint32_t a[4];
#pragma unroll
                for (int r4 = 0; r4 < 2; r4++) {
                    const uint32_t Wm = cm[r4][kk >> 1];
                    const uint32_t ba = Wm >> sh;
                    a[r4]     = hmax2_(hmul2_(Ph[r4], Qa), hmul2_(P2h[r4], Q2a)) & mask2(ba);
                    a[r4 + 2] = hmax2_(hmul2_(Ph[r4], Qb), hmul2_(P2h[r4], Q2b)) & mask2(ba >> 8);
                }
                mma16816(zc, a[0], a[1], a[2], a[3], ONES, ONES);
#pragma unroll
                for (int ntp = 0; ntp < 4; ntp++) {
                    uint32_t b0, b1, b2, b3;
                    ldsm_x4_t(b0, b1, b2, b3,
                              bbuf + SWZ((uint32_t)(kk * 2048 + brow * 128 +
                                                    (2 * ntp + bsel) * 16)));
                    mma16816(acc[2 * ntp + 0], a[0], a[1], a[2], a[3], b0, b1);
                    mma16816(acc[2 * ntp + 1], a[0], a[1], a[2], a[3], b2, b3);
                }
            }
        }
    }

    // ---- epilogue ----
    const float izlo = __frcp_rn(zc[0]);
    const float izhi = __frcp_rn(zc[2]);
    const int rlo = i0 + wid * 16 + qrow;
#pragma unroll
    for (int nt = 0; nt < 8; nt++) {
        const int col = head * 64 + nt * 8 + qcol;
        const float2 bv = *(const float2*)&bias[col];
        float2 o0, o1;
        o0.x = fmaf(acc[nt][0], izlo, bv.x);
        o0.y = fmaf(acc[nt][1], izlo, bv.y);
        o1.x = fmaf(acc[nt][2], izhi, bv.x);
        o1.y = fmaf(acc[nt][3], izhi, bv.y);
        *(float2*)&out[(size_t)rlo * FOUT + col] = o0;
        *(float2*)&out[(size_t)(rlo + 8) * FOUT + col] = o1;
    }
}

// ---------------------------------------------------------------------------
extern "C" void kernel_launch(void* const* d_in, const int* in_sizes, int n_in,
                              void* d_out, int out_size) {
    const float* x     = (const float*)d_in[0];
    const int*   adj   = (const int*)  d_in[1];
    const float* W     = (const float*)d_in[2];
    const float* a_src = (const float*)d_in[3];
    const float* a_dst = (const float*)d_in[4];
    const float* bias  = (const float*)d_in[5];
    float* out = (float*)d_out;

    cast_kernel<<<(X4 + W4) / 256, 256>>>(x, W);
    transform_kernel<<<dim3(NN / 128, FOUT / 64), 256>>>();
    attn_vec_kernel<<<(NN * HEADS) / 256, 256>>>(a_src, a_dst);
    pack_kernel<<<(NN * NWORDS) / 256, 256>>>(adj);
    aggregate_kernel<<<dim3(NN / BI, HEADS), 256, 32768>>>(bias, out);
}

// round 12
// speedup vs baseline: 121.6802x; 1.0029x over previous
#include <cuda_runtime.h>
#include <cuda_fp16.h>
#include <cstdint>

// ============================================================================
// SpatialGAT on GB300 — round 11: round 10 + fixed pack_kernel grid
//
// Key identity: softmax rows are scale-invariant =>
//   w'_ij = bit_ij * max(Q_j, R_i * Q2_j),  R_i = exp(-0.8 s_i)
//
// Stage 0: cast W -> f16
// Stage 1: h = x @ W via HMMA (x converted inline) -> g_hf f16
// Stage 2: R table (head-major) + Q/Q2 tables kk-swizzled
// Stage 3: pack adj -> bitmask via ballot (coalesced); grid = NN*NWORDS/64
// Stage 4: aggregation: A-fragments in regs, B cp.async double buffer,
//          Z via ones-mma, epilogue acc/Z + bias.
// ============================================================================

#define NN      8192
#define FOUT    256
#define FIN     256
#define HEADS   4
#define NEG_SLOPE 0.2f
#define BI      128
#define BJ      128
#define NCHUNK  (NN / BJ)
#define NWORDS  (NN / 32)
#define NBLK64  (NN / 64)

__device__ __half   g_Wf[FIN * FOUT];
__device__ __half   g_hf[NN * FOUT];
__device__ __half   g_RT[HEADS * NN];                 // exp(-0.8 s), head-major
__device__ uint32_t g_Qsw [HEADS * NBLK64 * 32];      // kk-swizzled f16 pairs
__device__ uint32_t g_Q2sw[HEADS * NBLK64 * 32];
__device__ unsigned g_adjb[NN * NWORDS];

// ---------------------------------------------------------------------------
__device__ __forceinline__ uint32_t smem_u32(const void* p) {
    uint32_t a;
    asm("{ .reg .u64 t; cvta.to.shared.u64 t, %1; cvt.u32.u64 %0, t; }"
        : "=r"(a) : "l"(p));
    return a;
}
__device__ __forceinline__ uint32_t hmul2_(uint32_t a, uint32_t b) {
    uint32_t d; asm("mul.f16x2 %0, %1, %2;" : "=r"(d) : "r"(a), "r"(b)); return d;
}
__device__ __forceinline__ uint32_t hmax2_(uint32_t a, uint32_t b) {
    uint32_t d; asm("max.f16x2 %0, %1, %2;" : "=r"(d) : "r"(a), "r"(b)); return d;
}
__device__ __forceinline__ uint32_t splat16(unsigned short h) {
    uint32_t r; asm("mov.b32 %0, {%1, %1};" : "=r"(r) : "h"(h)); return r;
}
// sign-extended 1-bit field -> 0 / 0xFFFFFFFF
__device__ __forceinline__ uint32_t bfe1s(uint32_t a, int pos) {
    uint32_t d; asm("bfe.s32 %0, %1, %2, 1;" : "=r"(d) : "r"(a), "r"(pos)); return d;
}
// (t0 & 0x0000FFFF) | (t1 & 0xFFFF0000) in one LOP3 (select by constant)
__device__ __forceinline__ uint32_t lop_mix(uint32_t t0, uint32_t t1) {
    uint32_t d;
    asm("lop3.b32 %0, %1, %2, 0x0000FFFF, 0xE4;" : "=r"(d) : "r"(t0), "r"(t1));
    return d;
}
__device__ __forceinline__ void ldsm_x4(uint32_t& r0, uint32_t& r1, uint32_t& r2,
                                        uint32_t& r3, uint32_t addr) {
    asm volatile("ldmatrix.sync.aligned.m8n8.x4.shared.b16 {%0,%1,%2,%3}, [%4];"
                 : "=r"(r0), "=r"(r1), "=r"(r2), "=r"(r3) : "r"(addr));
}
__device__ __forceinline__ void ldsm_x4_t(uint32_t& r0, uint32_t& r1, uint32_t& r2,
                                          uint32_t& r3, uint32_t addr) {
    asm volatile("ldmatrix.sync.aligned.m8n8.x4.trans.shared.b16 {%0,%1,%2,%3}, [%4];"
                 : "=r"(r0), "=r"(r1), "=r"(r2), "=r"(r3) : "r"(addr));
}
__device__ __forceinline__ void mma16816(float* c, uint32_t a0, uint32_t a1,
                                         uint32_t a2, uint32_t a3,
                                         uint32_t b0, uint32_t b1) {
    asm volatile(
        "mma.sync.aligned.m16n8k16.row.col.f32.f16.f16.f32 "
        "{%0,%1,%2,%3}, {%4,%5,%6,%7}, {%8,%9}, {%0,%1,%2,%3};"
        : "+f"(c[0]), "+f"(c[1]), "+f"(c[2]), "+f"(c[3])
        : "r"(a0), "r"(a1), "r"(a2), "r"(a3), "r"(b0), "r"(b1));
}
__device__ __forceinline__ void cp_async16(uint32_t dst, const void* src) {
    unsigned long long g;
    asm("cvta.to.global.u64 %0, %1;" : "=l"(g) : "l"(src));
    asm volatile("cp.async.ca.shared.global [%0], [%1], 16;" :: "r"(dst), "l"(g));
}
__device__ __forceinline__ void cp_commit() {
    asm volatile("cp.async.commit_group;" ::: "memory");
}
__device__ __forceinline__ void cp_wait_all() {
    asm volatile("cp.async.wait_group 0;" ::: "memory");
}
#define SWZ(off) ((off) ^ (((off) >> 3) & 0x70))

// ---------------------------------------------------------------------------
// Stage 0: cast W -> f16
// ---------------------------------------------------------------------------
#define W4   (FIN * FOUT / 4)
__global__ void __launch_bounds__(256) cast_w_kernel(const float* __restrict__ W) {
    int u = blockIdx.x * 256 + threadIdx.x;
    if (u < W4) {
        float4 v = ((const float4*)W)[u];
        __half2 a = __floats2half2_rn(v.x, v.y);
        __half2 b = __floats2half2_rn(v.z, v.w);
        uint2 o; o.x = *(uint32_t*)&a; o.y = *(uint32_t*)&b;
        ((uint2*)g_Wf)[u] = o;
    }
}

// ---------------------------------------------------------------------------
// Stage 1: h = x @ W via HMMA; x converted f32->f16 while staging.
// ---------------------------------------------------------------------------
__global__ void __launch_bounds__(256) transform_kernel(const float* __restrict__ x) {
    __shared__ __align__(16) unsigned char ts[16384 + 8192];
    const uint32_t sbx = smem_u32(ts);
    const uint32_t sbw = sbx + 16384;
    const int tid = threadIdx.x;
    const int lane = tid & 31, wid = tid >> 5;
    const int i0 = blockIdx.x * 128, n0 = blockIdx.y * 64;

    const int arow = (lane & 7) + ((lane >> 3) & 1) * 8;
    const uint32_t a_base = (uint32_t)((wid * 16 + arow) * 128 + (lane >> 4) * 16);
    const int brow = (lane & 7) + ((lane >> 3) & 1) * 8;
    const int bsel = (lane >> 4) & 1;
    const int qrow = lane >> 2, qcol = (lane & 3) * 2;

    float acc[8][4];
#pragma unroll
    for (int nt = 0; nt < 8; nt++)
#pragma unroll
        for (int c = 0; c < 4; c++) acc[nt][c] = 0.f;

    for (int kc = 0; kc < 4; kc++) {
        const int k0 = kc * 64;
#pragma unroll
        for (int u = 0; u < 4; u++) {
            int unit = tid + u * 256;
            int row = unit >> 3, seg = unit & 7;
            const float* xp = &x[(size_t)(i0 + row) * FIN + k0 + seg * 8];
            float4 f0 = *(const float4*)xp;
            float4 f1 = *(const float4*)(xp + 4);
            __half2 h0 = __floats2half2_rn(f0.x, f0.y);
            __half2 h1 = __floats2half2_rn(f0.z, f0.w);
            __half2 h2 = __floats2half2_rn(f1.x, f1.y);
            __half2 h3 = __floats2half2_rn(f1.z, f1.w);
            uint4 v;
            v.x = *(uint32_t*)&h0; v.y = *(uint32_t*)&h1;
            v.z = *(uint32_t*)&h2; v.w = *(uint32_t*)&h3;
            *(uint4*)(ts + SWZ((uint32_t)(row * 128 + seg * 16))) = v;
        }
#pragma unroll
        for (int u = 0; u < 2; u++) {
            int unit = tid + u * 256;
            int row = unit >> 3, seg = unit & 7;
            uint4 v = *(const uint4*)&g_Wf[(size_t)(k0 + row) * FOUT + n0 + seg * 8];
            *(uint4*)(ts + 16384 + SWZ((uint32_t)(row * 128 + seg * 16))) = v;
        }
        __syncthreads();
#pragma unroll
        for (int kk = 0; kk < 4; kk++) {
            uint32_t a0, a1, a2, a3;
            ldsm_x4(a0, a1, a2, a3, sbx + SWZ(a_base + kk * 32));
#pragma unroll
            for (int ntp = 0; ntp < 4; ntp++) {
                uint32_t b0, b1, b2, b3;
                ldsm_x4_t(b0, b1, b2, b3,
                          sbw + SWZ((uint32_t)(kk * 2048 + brow * 128 +
                                               (2 * ntp + bsel) * 16)));
                mma16816(acc[2 * ntp + 0], a0, a1, a2, a3, b0, b1);
                mma16816(acc[2 * ntp + 1], a0, a1, a2, a3, b2, b3);
            }
        }
        __syncthreads();
    }
    const int rlo = i0 + wid * 16 + qrow;
#pragma unroll
    for (int nt = 0; nt < 8; nt++) {
        const int col = n0 + nt * 8 + qcol;
        __half2 lo = __floats2half2_rn(acc[nt][0], acc[nt][1]);
        __half2 hi = __floats2half2_rn(acc[nt][2], acc[nt][3]);
        *(uint32_t*)&g_hf[(size_t)rlo * FOUT + col] = *(uint32_t*)&lo;
        *(uint32_t*)&g_hf[(size_t)(rlo + 8) * FOUT + col] = *(uint32_t*)&hi;
    }
}

// ---------------------------------------------------------------------------
// Stage 2: R table (head-major) + Q/Q2 tables kk-swizzled
// ---------------------------------------------------------------------------
__global__ void __launch_bounds__(256) attn_vec_kernel(const float* __restrict__ a_src,
                                                       const float* __restrict__ a_dst) {
    int idx = blockIdx.x * blockDim.x + threadIdx.x;
    if (idx >= NN * HEADS) return;
    int n = idx >> 2, h = idx & 3;
    const __half2* hp = (const __half2*)&g_hf[(size_t)n * FOUT + h * 64];
    const float* as = &a_src[h * 64];
    const float* ad = &a_dst[h * 64];
    float s = 0.f, d = 0.f;
#pragma unroll 8
    for (int k = 0; k < 32; k++) {
        float2 v = __half22float2(hp[k]);
        s = fmaf(v.x, as[2 * k], s);     s = fmaf(v.y, as[2 * k + 1], s);
        d = fmaf(v.x, ad[2 * k], d);     d = fmaf(v.y, ad[2 * k + 1], d);
    }
    g_RT[h * NN + n] = __float2half_rn(expf(-0.8f * s));
    int blk = n >> 6, c = n & 63;
    int kk = c >> 4, within = c & 15;
    int m = within >> 1, hs = within & 1;
    size_t widx = ((size_t)(h * NBLK64 + blk) * 32 + m * 4 + kk) * 2 + hs;
    ((__half*)g_Qsw )[widx] = __float2half_rn(expf(d));
    ((__half*)g_Q2sw)[widx] = __float2half_rn(expf(NEG_SLOPE * d));
}

// ---------------------------------------------------------------------------
// Stage 3: pack adj via ballot. Warp = 8 words (256 ints); block = 64 words.
// grid = NN*NWORDS/64 blocks.
// ---------------------------------------------------------------------------
__global__ void __launch_bounds__(256) pack_kernel(const int* __restrict__ adj) {
    const int gw = (blockIdx.x * 256 + threadIdx.x) >> 5;
    const int lane = threadIdx.x & 31;
    const size_t base = (size_t)gw * 256;
    const int* p = adj + base;
    int v[8];
#pragma unroll
    for (int it = 0; it < 8; it++) v[it] = p[it * 32 + lane];
    unsigned w[8];
#pragma unroll
    for (int it = 0; it < 8; it++) w[it] = __ballot_sync(0xFFFFFFFFu, v[it] != 0);
    if (lane == 0) {
        *(uint4*)&g_adjb[base / 32]     = make_uint4(w[0], w[1], w[2], w[3]);
        *(uint4*)&g_adjb[base / 32 + 4] = make_uint4(w[4], w[5], w[6], w[7]);
    }
}

// ---------------------------------------------------------------------------
// Stage 4: HMMA aggregation. w' = bit * max(Q, R*Q2). B double buffer 2x16KB.
// ---------------------------------------------------------------------------
extern __shared__ unsigned char dsm[];

__global__ void __launch_bounds__(256, 2)
aggregate_kernel(const float* __restrict__ bias, float* __restrict__ out) {
    const int tid  = threadIdx.x;
    const int lane = tid & 31;
    const int wid  = tid >> 5;
    const int head = blockIdx.y;
    const int i0   = blockIdx.x * BI;
    const uint32_t sb = smem_u32(dsm);

    uint32_t bst[4];
    int jr[4], sg[4];
#pragma unroll
    for (int u = 0; u < 4; u++) {
        int unit = tid + u * 256;
        jr[u] = unit >> 3; sg[u] = unit & 7;
        bst[u] = SWZ((uint32_t)(jr[u] * 128 + sg[u] * 16));
    }

    const int brow = (lane & 7) + ((lane >> 3) & 1) * 8;
    const int bsel = (lane >> 4) & 1;
    const int qrow = lane >> 2;
    const int qcol = (lane & 3) * 2;

    int rows[2];
    uint32_t Rh[2];
#pragma unroll
    for (int r4 = 0; r4 < 2; r4++) {
        rows[r4] = wid * 16 + r4 * 8 + qrow;
        Rh[r4] = splat16(__half_as_ushort(g_RT[head * NN + i0 + rows[r4]]));
    }

    float acc[8][4];
#pragma unroll
    for (int nt = 0; nt < 8; nt++)
#pragma unroll
        for (int c = 0; c < 4; c++) acc[nt][c] = 0.f;
    float zc[4] = {0.f, 0.f, 0.f, 0.f};
    const uint32_t ONES = 0x3C003C00u;

#pragma unroll
    for (int u = 0; u < 4; u++)
        cp_async16(sb + bst[u], &g_hf[(size_t)jr[u] * FOUT + head * 64 + sg[u] * 8]);
    cp_commit();

    uint4 mrow[2];
#pragma unroll
    for (int r4 = 0; r4 < 2; r4++)
        mrow[r4] = *(const uint4*)&g_adjb[(size_t)(i0 + rows[r4]) * NWORDS];

    const uint32_t* Qsw  = &g_Qsw [head * NBLK64 * 32];
    const uint32_t* Q2sw = &g_Q2sw[head * NBLK64 * 32];
    const int moff = (lane & 3) * 4;

    for (int t = 0; t < NCHUNK; t++) {
        const int b = t & 1;
        const int j0 = t * BJ;
        const uint32_t bbuf = sb + (b ? 16384u : 0u);

        cp_wait_all();
        __syncthreads();

        {
            const int tn = (t + 1 < NCHUNK) ? t + 1 : t;
            const int jn = tn * BJ;
            const uint32_t obuf = sb + (b ? 0u : 16384u);
#pragma unroll
            for (int u = 0; u < 4; u++)
                cp_async16(obuf + bst[u],
                           &g_hf[(size_t)(jn + jr[u]) * FOUT + head * 64 + sg[u] * 8]);
            cp_commit();
        }
        uint32_t cm[2][4];
#pragma unroll
        for (int r4 = 0; r4 < 2; r4++) {
            cm[r4][0] = mrow[r4].x; cm[r4][1] = mrow[r4].y;
            cm[r4][2] = mrow[r4].z; cm[r4][3] = mrow[r4].w;
        }
        {
            const int tn = (t + 1 < NCHUNK) ? t + 1 : t;
#pragma unroll
            for (int r4 = 0; r4 < 2; r4++)
                mrow[r4] = *(const uint4*)&g_adjb[(size_t)(i0 + rows[r4]) * NWORDS + tn * 4];
        }

#pragma unroll
        for (int b64 = 0; b64 < 2; b64++) {
            const int base = ((j0 >> 6) + b64) * 32;
            const uint4 Qa4  = *(const uint4*)&Qsw [base + moff];
            const uint4 Qb4  = *(const uint4*)&Qsw [base + 16 + moff];
            const uint4 Q2a4 = *(const uint4*)&Q2sw[base + moff];
            const uint4 Q2b4 = *(const uint4*)&Q2sw[base + 16 + moff];
            uint32_t QaA[4]  = {Qa4.x, Qa4.y, Qa4.z, Qa4.w};
            uint32_t QbA[4]  = {Qb4.x, Qb4.y, Qb4.z, Qb4.w};
            uint32_t Q2aA[4] = {Q2a4.x, Q2a4.y, Q2a4.z, Q2a4.w};
            uint32_t Q2bA[4] = {Q2b4.x, Q2b4.y, Q2b4.z, Q2b4.w};

#pragma unroll
            for (int k4 = 0; k4 < 4; k4++) {
                const int kk = b64 * 4 + k4;
                const uint32_t Qa = QaA[k4], Qb = QbA[k4];
                const uint32_t Q2a = Q2aA[k4], Q2b = Q2bA[k4];
                const int shb = (kk & 1) << 4;

                uint32_t a[4];
#pragma unroll
                for (int r4 = 0; r4 < 2; r4++) {
                    const uint32_t Wm = cm[r4][kk >> 1];
                    uint32_t t0 = bfe1s(Wm, qcol + shb);
                    uint32_t t1 = bfe1s(Wm, qcol + shb + 1);
                    a[r4] = hmax2_(Qa, hmul2_(Rh[r4], Q2a)) & lop_mix(t0, t1);
                    uint32_t t2 = bfe1s(Wm, qcol + shb + 8);
                    uint32_t t3 = bfe1s(Wm, qcol + shb + 9);
                    a[r4 + 2] = hmax2_(Qb, hmul2_(Rh[r4], Q2b)) & lop_mix(t2, t3);
                }
                mma16816(zc, a[0], a[1], a[2], a[3], ONES, ONES);
#pragma unroll
                for (int ntp = 0; ntp < 4; ntp++) {
                    uint32_t b0, b1, b2, b3;
                    ldsm_x4_t(b0, b1, b2, b3,
                              bbuf + SWZ((uint32_t)(kk * 2048 + brow * 128 +
                                                    (2 * ntp + bsel) * 16)));
                    mma16816(acc[2 * ntp + 0], a[0], a[1], a[2], a[3], b0, b1);
                    mma16816(acc[2 * ntp + 1], a[0], a[1], a[2], a[3], b2, b3);
                }
            }
        }
    }

    const float izlo = __frcp_rn(zc[0]);
    const float izhi = __frcp_rn(zc[2]);
    const int rlo = i0 + wid * 16 + qrow;
#pragma unroll
    for (int nt = 0; nt < 8; nt++) {
        const int col = head * 64 + nt * 8 + qcol;
        const float2 bv = *(const float2*)&bias[col];
        float2 o0, o1;
        o0.x = fmaf(acc[nt][0], izlo, bv.x);
        o0.y = fmaf(acc[nt][1], izlo, bv.y);
        o1.x = fmaf(acc[nt][2], izhi, bv.x);
        o1.y = fmaf(acc[nt][3], izhi, bv.y);
        *(float2*)&out[(size_t)rlo * FOUT + col] = o0;
        *(float2*)&out[(size_t)(rlo + 8) * FOUT + col] = o1;
    }
}

// ---------------------------------------------------------------------------
extern "C" void kernel_launch(void* const* d_in, const int* in_sizes, int n_in,
                              void* d_out, int out_size) {
    const float* x     = (const float*)d_in[0];
    const int*   adj   = (const int*)  d_in[1];
    const float* W     = (const float*)d_in[2];
    const float* a_src = (const float*)d_in[3];
    const float* a_dst = (const float*)d_in[4];
    const float* bias  = (const float*)d_in[5];
    float* out = (float*)d_out;

    pack_kernel<<<(NN * NWORDS) / 64, 256>>>(adj);   // 32768 blocks: 64 words each
    cast_w_kernel<<<W4 / 256, 256>>>(W);
    transform_kernel<<<dim3(NN / 128, FOUT / 64), 256>>>(x);
    attn_vec_kernel<<<(NN * HEADS) / 256, 256>>>(a_src, a_dst);
    aggregate_kernel<<<dim3(NN / BI, HEADS), 256, 32768>>>(bias, out);
}